// round 1
// baseline (speedup 1.0000x reference)
#include <cuda_runtime.h>
#include <cuda_bf16.h>
#include <cstdint>

// Problem constants (fixed by the dataset)
#define S_LEN 2048
#define H_DIM 2048
#define NH    32
#define NKV   8
#define HD    64
#define QKV_COLS ((NH + 2*NKV) * HD)   // 3072

// ---------------------------------------------------------------------------
// Scratch (allocation-free rule: __device__ globals)
// ---------------------------------------------------------------------------
__device__ float g_qkv[(size_t)S_LEN * QKV_COLS];   // 24 MB
__device__ float g_y  [(size_t)S_LEN * H_DIM];      // 16 MB

// ---------------------------------------------------------------------------
// Generic TN SGEMM: C[m][n] = sum_k A[m][k] * B[n][k]
// A: MxK row-major, B: NxK row-major, C: MxN row-major.
// BM=BN=128, BK=16, 256 threads, 8x8 micro-tile per thread.
// M, N, K must be multiples of 128/128/16 (true for all our shapes).
// ---------------------------------------------------------------------------
__global__ __launch_bounds__(256) void sgemm_tn_kernel(
    const float* __restrict__ A, const float* __restrict__ B,
    float* __restrict__ C, int M, int N, int K)
{
    __shared__ float As[16][128];
    __shared__ float Bs[16][128];

    const int tid = threadIdx.x;
    const int tx  = tid & 15;        // 0..15
    const int ty  = tid >> 4;        // 0..15
    const int bm  = blockIdx.y * 128;
    const int bn  = blockIdx.x * 128;

    const float* Ablk = A + (size_t)bm * K;
    const float* Bblk = B + (size_t)bn * K;

    float acc[8][8];
#pragma unroll
    for (int i = 0; i < 8; i++)
#pragma unroll
        for (int j = 0; j < 8; j++) acc[i][j] = 0.f;

    for (int k0 = 0; k0 < K; k0 += 16) {
        // Load 128x16 tiles of A and B (512 float4 each; 2 per thread)
#pragma unroll
        for (int r = 0; r < 2; r++) {
            int p   = tid + r * 256;       // 0..511
            int row = p >> 2;              // 0..127
            int col = (p & 3) * 4;         // 0,4,8,12
            float4 va = *reinterpret_cast<const float4*>(Ablk + (size_t)row * K + k0 + col);
            As[col + 0][row] = va.x;
            As[col + 1][row] = va.y;
            As[col + 2][row] = va.z;
            As[col + 3][row] = va.w;
            float4 vb = *reinterpret_cast<const float4*>(Bblk + (size_t)row * K + k0 + col);
            Bs[col + 0][row] = vb.x;
            Bs[col + 1][row] = vb.y;
            Bs[col + 2][row] = vb.z;
            Bs[col + 3][row] = vb.w;
        }
        __syncthreads();

#pragma unroll
        for (int kk = 0; kk < 16; kk++) {
            float a[8], b[8];
#pragma unroll
            for (int i = 0; i < 8; i++) a[i] = As[kk][ty * 8 + i];
#pragma unroll
            for (int j = 0; j < 8; j++) b[j] = Bs[kk][tx * 8 + j];
#pragma unroll
            for (int i = 0; i < 8; i++)
#pragma unroll
                for (int j = 0; j < 8; j++)
                    acc[i][j] += a[i] * b[j];
        }
        __syncthreads();
    }

#pragma unroll
    for (int i = 0; i < 8; i++) {
        int row = bm + ty * 8 + i;
        float* crow = C + (size_t)row * N + bn + tx * 8;
#pragma unroll
        for (int j = 0; j < 8; j += 4) {
            float4 v = make_float4(acc[i][j], acc[i][j+1], acc[i][j+2], acc[i][j+3]);
            *reinterpret_cast<float4*>(crow + j) = v;
        }
    }
}

// ---------------------------------------------------------------------------
// RoPE, interleaved pairing (matches reference apply_rope exactly):
//   (x0,x1) -> (x0*c - x1*s, x1*c + x0*s) with (x0,x1) = elements (2d, 2d+1)
// Applied in-place to Q (heads 0..31) and K (heads 0..7 at col offset 2048).
// freqs_cis layout: [S, HD/2, 2] -> fc[s*64 + d*2 + {0=cos,1=sin}]
// ---------------------------------------------------------------------------
__global__ __launch_bounds__(256) void rope_kernel(
    float* __restrict__ qkv, const float* __restrict__ fc)
{
    int idx = blockIdx.x * blockDim.x + threadIdx.x;   // one thread per pair
    // total pairs = S * (NH + NKV) * (HD/2) = 2048 * 40 * 32
    int d = idx & 31;              // pair index 0..31
    int h = (idx >> 5) % 40;       // 0..39 (0..31 = q heads, 32..39 = k heads)
    int s = idx / (40 * 32);
    if (s >= S_LEN) return;

    int col = (h < NH) ? h * HD : (NH * HD) + (h - NH) * HD;
    float c  = fc[s * 64 + d * 2 + 0];
    float sn = fc[s * 64 + d * 2 + 1];
    float* p = qkv + (size_t)s * QKV_COLS + col + 2 * d;
    float x0 = p[0], x1 = p[1];
    p[0] = x0 * c - x1 * sn;
    p[1] = x1 * c + x0 * sn;
}

// ---------------------------------------------------------------------------
// FP32 flash attention, causal, GQA (4 q-heads share each kv head).
// Block: one (q-head, 64-row q tile). 256 threads = 16x16 grid, each thread
// owns a 4x4 micro-tile of the 64x64 score / 64x64 output tiles.
// smem (dynamic, 68 KB): Qt[64][68] (d-major), Kt[64][68] (d-major),
//                        Vs[64][68] (row-major), Pt[64][68] (j-major).
// ---------------------------------------------------------------------------
#define FA_W 68   // padded row width (floats); keeps 16B alignment, breaks bank stride

__global__ __launch_bounds__(256) void flash_kernel(
    const float* __restrict__ qkv, float* __restrict__ Y)
{
    extern __shared__ float sm[];
    float* Qt = sm;                  // [d][i]
    float* Kt = Qt + 64 * FA_W;      // [d][j]
    float* Vs = Kt + 64 * FA_W;      // [j][d]
    float* Pt = Vs + 64 * FA_W;      // [j][i]

    const int h  = blockIdx.y;       // q head 0..31
    const int kh = h >> 2;           // kv head 0..7
    const int qt = blockIdx.x;       // q tile 0..31
    const int q0 = qt * 64;

    const int tid = threadIdx.x;
    const int tx  = tid & 15;
    const int ty  = tid >> 4;

    // --- load Q tile transposed: Qt[d][i] = qkv[q0+i][h*64+d] ---
#pragma unroll
    for (int r4 = 0; r4 < 4; r4++) {
        int p   = tid + r4 * 256;    // 0..1023
        int row = p >> 4;            // 0..63
        int col = (p & 15) * 4;      // 0..60
        float4 v = *reinterpret_cast<const float4*>(
            qkv + (size_t)(q0 + row) * QKV_COLS + h * HD + col);
        Qt[(col + 0) * FA_W + row] = v.x;
        Qt[(col + 1) * FA_W + row] = v.y;
        Qt[(col + 2) * FA_W + row] = v.z;
        Qt[(col + 3) * FA_W + row] = v.w;
    }

    float m[4], l[4], o[4][4];
#pragma unroll
    for (int i = 0; i < 4; i++) {
        m[i] = -1e30f; l[i] = 0.f;
#pragma unroll
        for (int j = 0; j < 4; j++) o[i][j] = 0.f;
    }

    const float SCALE = 0.125f;   // 1/sqrt(64)

    for (int jt = 0; jt <= qt; jt++) {
        const int j0 = jt * 64;
        __syncthreads();   // protect Kt/Vs (prev reads) and Qt (first iter)

        // --- load K tile transposed + V tile row-major ---
#pragma unroll
        for (int r4 = 0; r4 < 4; r4++) {
            int p   = tid + r4 * 256;
            int row = p >> 4;
            int col = (p & 15) * 4;
            const float* base = qkv + (size_t)(j0 + row) * QKV_COLS + kh * HD;
            float4 kv = *reinterpret_cast<const float4*>(base + NH * HD + col);
            Kt[(col + 0) * FA_W + row] = kv.x;
            Kt[(col + 1) * FA_W + row] = kv.y;
            Kt[(col + 2) * FA_W + row] = kv.z;
            Kt[(col + 3) * FA_W + row] = kv.w;
            float4 vv = *reinterpret_cast<const float4*>(base + (NH + NKV) * HD + col);
            *reinterpret_cast<float4*>(&Vs[row * FA_W + col]) = vv;
        }
        __syncthreads();

        // --- scores: s[i][j] = sum_d Qt[d][ty*4+i] * Kt[d][tx*4+j] ---
        float s[4][4];
#pragma unroll
        for (int i = 0; i < 4; i++)
#pragma unroll
            for (int j = 0; j < 4; j++) s[i][j] = 0.f;

#pragma unroll 8
        for (int d = 0; d < 64; d++) {
            float4 a = *reinterpret_cast<const float4*>(&Qt[d * FA_W + ty * 4]);
            float4 b = *reinterpret_cast<const float4*>(&Kt[d * FA_W + tx * 4]);
            float av[4] = {a.x, a.y, a.z, a.w};
            float bv[4] = {b.x, b.y, b.z, b.w};
#pragma unroll
            for (int i = 0; i < 4; i++)
#pragma unroll
                for (int j = 0; j < 4; j++)
                    s[i][j] += av[i] * bv[j];
        }

#pragma unroll
        for (int i = 0; i < 4; i++)
#pragma unroll
            for (int j = 0; j < 4; j++) s[i][j] *= SCALE;

        // --- causal mask, only needed on the diagonal tile ---
        if (jt == qt) {
#pragma unroll
            for (int i = 0; i < 4; i++) {
                int gi = ty * 4 + i;     // local row == local causal limit
#pragma unroll
                for (int j = 0; j < 4; j++)
                    if (tx * 4 + j > gi) s[i][j] = -1e30f;
            }
        }

        // --- online softmax update (row groups = 16 contiguous lanes) ---
#pragma unroll
        for (int i = 0; i < 4; i++) {
            float rm = fmaxf(fmaxf(s[i][0], s[i][1]), fmaxf(s[i][2], s[i][3]));
#pragma unroll
            for (int off = 8; off > 0; off >>= 1)
                rm = fmaxf(rm, __shfl_xor_sync(0xffffffffu, rm, off, 16));
            float mn = fmaxf(m[i], rm);
            float sc = __expf(m[i] - mn);
            float rs = 0.f;
#pragma unroll
            for (int j = 0; j < 4; j++) {
                float pv = __expf(s[i][j] - mn);
                s[i][j] = pv;
                rs += pv;
            }
#pragma unroll
            for (int off = 8; off > 0; off >>= 1)
                rs += __shfl_xor_sync(0xffffffffu, rs, off, 16);
            l[i] = l[i] * sc + rs;
            m[i] = mn;
#pragma unroll
            for (int j = 0; j < 4; j++) o[i][j] *= sc;
        }

        // --- store P transposed: Pt[j][i] ---
#pragma unroll
        for (int j = 0; j < 4; j++) {
            float4 v = make_float4(s[0][j], s[1][j], s[2][j], s[3][j]);
            *reinterpret_cast<float4*>(&Pt[(tx * 4 + j) * FA_W + ty * 4]) = v;
        }
        __syncthreads();

        // --- O += P @ V : o[i][d] += Pt[j][ty*4+i] * Vs[j][tx*4+d] ---
#pragma unroll 8
        for (int j = 0; j < 64; j++) {
            float4 a = *reinterpret_cast<const float4*>(&Pt[j * FA_W + ty * 4]);
            float4 b = *reinterpret_cast<const float4*>(&Vs[j * FA_W + tx * 4]);
            float av[4] = {a.x, a.y, a.z, a.w};
            float bv[4] = {b.x, b.y, b.z, b.w};
#pragma unroll
            for (int i = 0; i < 4; i++)
#pragma unroll
                for (int j2 = 0; j2 < 4; j2++)
                    o[i][j2] += av[i] * bv[j2];
        }
    }

    // --- epilogue: Y[q0+i][h*64 + d] = o / l ---
#pragma unroll
    for (int i = 0; i < 4; i++) {
        float inv = 1.f / l[i];
        int row = q0 + ty * 4 + i;
        float4 v = make_float4(o[i][0] * inv, o[i][1] * inv,
                               o[i][2] * inv, o[i][3] * inv);
        *reinterpret_cast<float4*>(&Y[(size_t)row * H_DIM + h * HD + tx * 4]) = v;
    }
}

// ---------------------------------------------------------------------------
// kernel_launch
// Inputs (metadata order): x[1,2048,2048] f32, freqs_cis[2048,32,2] f32,
//                          mask (bool, unused — causal is hardcoded),
//                          Wqkv[3072,2048] f32, Wo[2048,2048] f32.
// Output: [1,2048,2048] f32.
// ---------------------------------------------------------------------------
extern "C" void kernel_launch(void* const* d_in, const int* in_sizes, int n_in,
                              void* d_out, int out_size)
{
    const float* x    = (const float*)d_in[0];
    const float* fc   = (const float*)d_in[1];
    const float* Wqkv = (const float*)d_in[3];
    const float* Wo   = (const float*)d_in[4];
    float* out = (float*)d_out;

    float* qkv_buf = nullptr;
    float* y_buf   = nullptr;
    cudaGetSymbolAddress((void**)&qkv_buf, g_qkv);
    cudaGetSymbolAddress((void**)&y_buf,   g_y);

    const size_t fa_smem = (size_t)4 * 64 * FA_W * sizeof(float); // 69632 B
    cudaFuncSetAttribute(flash_kernel,
                         cudaFuncAttributeMaxDynamicSharedMemorySize,
                         (int)fa_smem);

    // 1) QKV projection: g_qkv[2048,3072] = x @ Wqkv^T
    {
        dim3 grid(QKV_COLS / 128, S_LEN / 128);
        sgemm_tn_kernel<<<grid, 256>>>(x, Wqkv, qkv_buf, S_LEN, QKV_COLS, H_DIM);
    }

    // 2) RoPE on q and k in-place
    {
        int total = S_LEN * (NH + NKV) * (HD / 2);
        rope_kernel<<<(total + 255) / 256, 256>>>(qkv_buf, fc);
    }

    // 3) causal GQA flash attention -> g_y[2048,2048]
    {
        dim3 grid(S_LEN / 64, NH);
        flash_kernel<<<grid, 256, fa_smem>>>(qkv_buf, y_buf);
    }

    // 4) output projection: out = g_y @ Wo^T
    {
        dim3 grid(H_DIM / 128, S_LEN / 128);
        sgemm_tn_kernel<<<grid, 256>>>(y_buf, Wo, out, S_LEN, H_DIM, H_DIM);
    }
}

// round 3
// speedup vs baseline: 1.0076x; 1.0076x over previous
#include <cuda_runtime.h>
#include <cuda_bf16.h>
#include <cstdint>

// Problem constants (fixed by the dataset)
#define S_LEN 2048
#define H_DIM 2048
#define NH    32
#define NKV   8
#define HD    64
#define QKV_COLS ((NH + 2*NKV) * HD)   // 3072

// ---------------------------------------------------------------------------
// Scratch (allocation-free rule: __device__ globals)
// ---------------------------------------------------------------------------
__device__ float g_qkv[(size_t)S_LEN * QKV_COLS];   // 24 MB
__device__ float g_y  [(size_t)S_LEN * H_DIM];      // 16 MB
__device__ __align__(16) __nv_bfloat16 g_ahi[(size_t)S_LEN * H_DIM];
__device__ __align__(16) __nv_bfloat16 g_alo[(size_t)S_LEN * H_DIM];
__device__ __align__(16) __nv_bfloat16 g_bhi[(size_t)QKV_COLS * H_DIM];
__device__ __align__(16) __nv_bfloat16 g_blo[(size_t)QKV_COLS * H_DIM];

// ---------------------------------------------------------------------------
// Arch-agnostic PTX helpers (sm_80+ ISA only; no tcgen05 — ptxas targets sm_103)
// ---------------------------------------------------------------------------
__device__ __forceinline__ uint32_t smem_to_u32(const void* p) {
    uint32_t a;
    asm("{ .reg .u64 t; cvta.to.shared.u64 t, %1; cvt.u32.u64 %0, t; }"
        : "=r"(a) : "l"(p));
    return a;
}

__device__ __forceinline__ void cp_async16(uint32_t smem, const void* gptr) {
    asm volatile("cp.async.cg.shared.global [%0], [%1], 16;"
                 :: "r"(smem), "l"(__cvta_generic_to_global(gptr)) : "memory");
}
__device__ __forceinline__ void cp_commit() {
    asm volatile("cp.async.commit_group;" ::: "memory");
}
__device__ __forceinline__ void cp_wait1() {
    asm volatile("cp.async.wait_group 1;" ::: "memory");
}

__device__ __forceinline__ void ldsm4(uint32_t* r, uint32_t addr) {
    asm volatile("ldmatrix.sync.aligned.m8n8.x4.shared.b16 {%0,%1,%2,%3}, [%4];"
                 : "=r"(r[0]), "=r"(r[1]), "=r"(r[2]), "=r"(r[3]) : "r"(addr));
}
__device__ __forceinline__ void ldsm2(uint32_t* r, uint32_t addr) {
    asm volatile("ldmatrix.sync.aligned.m8n8.x2.shared.b16 {%0,%1}, [%2];"
                 : "=r"(r[0]), "=r"(r[1]) : "r"(addr));
}

__device__ __forceinline__ void mma16816(float* c, const uint32_t* a, const uint32_t* b) {
    asm volatile(
        "mma.sync.aligned.m16n8k16.row.col.f32.bf16.bf16.f32 "
        "{%0,%1,%2,%3}, {%4,%5,%6,%7}, {%8,%9}, {%0,%1,%2,%3};"
        : "+f"(c[0]), "+f"(c[1]), "+f"(c[2]), "+f"(c[3])
        : "r"(a[0]), "r"(a[1]), "r"(a[2]), "r"(a[3]), "r"(b[0]), "r"(b[1]));
}

// pack two f32 into bf16x2 (a -> upper, b -> lower)
__device__ __forceinline__ uint32_t pack_bf16x2(float hi_elem, float lo_elem) {
    uint32_t r;
    asm("cvt.rn.bf16x2.f32 %0, %1, %2;" : "=r"(r) : "f"(hi_elem), "f"(lo_elem));
    return r;
}

// ---------------------------------------------------------------------------
// Split fp32 -> (bf16 hi, bf16 lo) arrays, vectorized by 4
// ---------------------------------------------------------------------------
__global__ __launch_bounds__(256) void cvt_split_kernel(
    const float4* __restrict__ in, uint2* __restrict__ hi, uint2* __restrict__ lo, int n4)
{
    int i = blockIdx.x * blockDim.x + threadIdx.x;
    if (i >= n4) return;
    float4 f = in[i];
    uint32_t h01 = pack_bf16x2(f.y, f.x);
    uint32_t h23 = pack_bf16x2(f.w, f.z);
    float h0 = __uint_as_float(h01 << 16);
    float h1 = __uint_as_float(h01 & 0xffff0000u);
    float h2 = __uint_as_float(h23 << 16);
    float h3 = __uint_as_float(h23 & 0xffff0000u);
    uint32_t l01 = pack_bf16x2(f.y - h1, f.x - h0);
    uint32_t l23 = pack_bf16x2(f.w - h3, f.z - h2);
    hi[i] = make_uint2(h01, h23);
    lo[i] = make_uint2(l01, l23);
}

// ---------------------------------------------------------------------------
// HMMA TN GEMM, bf16x3 split, fp32 out:
//   C[m][n] = sum_k (Ah+Al)[m][k] * (Bh+Bl)[n][k]   (lo*lo dropped)
// CTA 128x128, BK=32, cp.async double-buffered, mma.sync.m16n8k16.
// 8 warps: warpM = w>>1 (4), warpN = w&1 (2); warp tile 32(M) x 64(N).
// smem rows padded to 40 bf16 (80B) -> conflict-free ldmatrix.
// ---------------------------------------------------------------------------
#define HM_BK     32
#define HM_ROWB   80                         // padded row bytes (40 bf16)
#define HM_TILE_B (128 * HM_ROWB)            // 10240 B per operand tile
#define HM_STAGE  (4 * HM_TILE_B)            // Ah, Al, Bh, Bl = 40960 B
#define HM_SMEM   (2 * HM_STAGE)             // 81920 B

__global__ __launch_bounds__(256, 1) void hmma_gemm_kernel(
    const __nv_bfloat16* __restrict__ Ah, const __nv_bfloat16* __restrict__ Al,
    const __nv_bfloat16* __restrict__ Bh, const __nv_bfloat16* __restrict__ Bl,
    float* __restrict__ C, int M, int N, int K)
{
    extern __shared__ char smem[];
    const uint32_t sbase = smem_to_u32(smem);

    const int tid  = threadIdx.x;
    const int wid  = tid >> 5;
    const int lane = tid & 31;
    const int warpM = wid >> 1;         // 0..3
    const int warpN = wid & 1;          // 0..1
    const int bm = blockIdx.y * 128;
    const int bn = blockIdx.x * 128;

    // --- per-thread cp.async geometry: p = tid + i*256 -> row = p>>2, chunk = p&3
    const int ldrow0 = tid >> 2;        // 0..63
    const int ldc    = (tid & 3) * 16;  // byte chunk in row (0..48)
    const __nv_bfloat16* srcs[4] = { Ah, Al, Bh, Bl };

    // --- ldmatrix lane address bases (byte offsets within a tile)
    // A: 16x16 tiles, x4: lanes 0-7 rows0-7@klo, 8-15 rows8-15@klo, 16-23 rows0-7@khi, 24-31 rows8-15@khi
    const uint32_t aAddrBase = (uint32_t)(warpM * 32 + (lane & 15)) * HM_ROWB + (lane >> 4) * 16;
    // B: x2: lanes 0-7 n-rows@klo, lanes 8-15 n-rows@khi (lanes 16+ ignored; keep valid)
    const uint32_t bAddrBase = (uint32_t)(warpN * 64 + (lane & 7)) * HM_ROWB + ((lane >> 3) & 1) * 16;

    float acc[2][8][4];
#pragma unroll
    for (int m = 0; m < 2; m++)
#pragma unroll
        for (int n = 0; n < 8; n++)
#pragma unroll
            for (int q = 0; q < 4; q++) acc[m][n][q] = 0.f;

    const int nchunk = K / HM_BK;

    // ---- stage loader
    auto load_stage = [&](int s, int c) {
        const int k0 = c * HM_BK;
        const uint32_t st = sbase + s * HM_STAGE;
#pragma unroll
        for (int t = 0; t < 4; t++) {
            const int rowbase = (t < 2) ? bm : bn;
            const __nv_bfloat16* src = srcs[t];
#pragma unroll
            for (int i = 0; i < 2; i++) {
                const int row = ldrow0 + i * 64;
                const __nv_bfloat16* g = src + (size_t)(rowbase + row) * K + k0 + (ldc >> 1);
                cp_async16(st + t * HM_TILE_B + (uint32_t)row * HM_ROWB + ldc, g);
            }
        }
    };

    // ---- prologue: stage 0 and 1 in flight
    load_stage(0, 0); cp_commit();
    if (nchunk > 1) { load_stage(1, 1); }
    cp_commit();
    cp_wait1();            // stage 0 ready
    __syncthreads();

    for (int c = 0; c < nchunk; c++) {
        const int s = c & 1;
        const uint32_t st = sbase + s * HM_STAGE;
        const uint32_t sAh = st + aAddrBase;
        const uint32_t sAl = sAh + HM_TILE_B;
        const uint32_t sBh = st + 2 * HM_TILE_B + bAddrBase;
        const uint32_t sBl = sBh + HM_TILE_B;

#pragma unroll
        for (int ks = 0; ks < 2; ks++) {
            const uint32_t ko = ks * 32;      // 16 bf16 = 32 bytes
            uint32_t ah[2][4], al[2][4];
            ldsm4(ah[0], sAh + ko);
            ldsm4(ah[1], sAh + 16 * HM_ROWB + ko);
            ldsm4(al[0], sAl + ko);
            ldsm4(al[1], sAl + 16 * HM_ROWB + ko);
#pragma unroll
            for (int n = 0; n < 8; n++) {
                uint32_t bh[2], bl[2];
                ldsm2(bh, sBh + (uint32_t)n * 8 * HM_ROWB + ko);
                ldsm2(bl, sBl + (uint32_t)n * 8 * HM_ROWB + ko);
#pragma unroll
                for (int m = 0; m < 2; m++) {
                    mma16816(acc[m][n], ah[m], bh);
                    mma16816(acc[m][n], ah[m], bl);
                    mma16816(acc[m][n], al[m], bh);
                }
            }
        }
        __syncthreads();                       // everyone done reading stage s
        if (c + 2 < nchunk) load_stage(s, c + 2);
        cp_commit();                           // (possibly empty group)
        cp_wait1();                            // stage for chunk c+1 ready
        __syncthreads();
    }

    // ---- epilogue: fragment -> global (float2 stores)
    const int qrow = lane >> 2;               // 0..7
    const int qcol = (lane & 3) * 2;          // 0,2,4,6
#pragma unroll
    for (int m = 0; m < 2; m++) {
        const int row0 = bm + warpM * 32 + m * 16 + qrow;
#pragma unroll
        for (int n = 0; n < 8; n++) {
            const int col = bn + warpN * 64 + n * 8 + qcol;
            *reinterpret_cast<float2*>(C + (size_t)row0 * N + col) =
                make_float2(acc[m][n][0], acc[m][n][1]);
            *reinterpret_cast<float2*>(C + (size_t)(row0 + 8) * N + col) =
                make_float2(acc[m][n][2], acc[m][n][3]);
        }
    }
}

// ---------------------------------------------------------------------------
// RoPE, interleaved pairing (matches reference apply_rope exactly)
// ---------------------------------------------------------------------------
__global__ __launch_bounds__(256) void rope_kernel(
    float* __restrict__ qkv, const float* __restrict__ fc)
{
    int idx = blockIdx.x * blockDim.x + threadIdx.x;
    int d = idx & 31;
    int h = (idx >> 5) % 40;
    int s = idx / (40 * 32);
    if (s >= S_LEN) return;

    int col = (h < NH) ? h * HD : (NH * HD) + (h - NH) * HD;
    float c  = fc[s * 64 + d * 2 + 0];
    float sn = fc[s * 64 + d * 2 + 1];
    float* p = qkv + (size_t)s * QKV_COLS + col + 2 * d;
    float x0 = p[0], x1 = p[1];
    p[0] = x0 * c - x1 * sn;
    p[1] = x1 * c + x0 * sn;
}

// ---------------------------------------------------------------------------
// FP32 flash attention, causal, GQA (known-good from round 1)
// ---------------------------------------------------------------------------
#define FA_W 68

__global__ __launch_bounds__(256) void flash_kernel(
    const float* __restrict__ qkv, float* __restrict__ Y)
{
    extern __shared__ float sm[];
    float* Qt = sm;
    float* Kt = Qt + 64 * FA_W;
    float* Vs = Kt + 64 * FA_W;
    float* Pt = Vs + 64 * FA_W;

    const int h  = blockIdx.y;
    const int kh = h >> 2;
    const int qt = blockIdx.x;
    const int q0 = qt * 64;

    const int tid = threadIdx.x;
    const int tx  = tid & 15;
    const int ty  = tid >> 4;

#pragma unroll
    for (int r4 = 0; r4 < 4; r4++) {
        int p   = tid + r4 * 256;
        int row = p >> 4;
        int col = (p & 15) * 4;
        float4 v = *reinterpret_cast<const float4*>(
            qkv + (size_t)(q0 + row) * QKV_COLS + h * HD + col);
        Qt[(col + 0) * FA_W + row] = v.x;
        Qt[(col + 1) * FA_W + row] = v.y;
        Qt[(col + 2) * FA_W + row] = v.z;
        Qt[(col + 3) * FA_W + row] = v.w;
    }

    float m[4], l[4], o[4][4];
#pragma unroll
    for (int i = 0; i < 4; i++) {
        m[i] = -1e30f; l[i] = 0.f;
#pragma unroll
        for (int j = 0; j < 4; j++) o[i][j] = 0.f;
    }

    const float SCALE = 0.125f;

    for (int jt = 0; jt <= qt; jt++) {
        const int j0 = jt * 64;
        __syncthreads();

#pragma unroll
        for (int r4 = 0; r4 < 4; r4++) {
            int p   = tid + r4 * 256;
            int row = p >> 4;
            int col = (p & 15) * 4;
            const float* base = qkv + (size_t)(j0 + row) * QKV_COLS + kh * HD;
            float4 kv = *reinterpret_cast<const float4*>(base + NH * HD + col);
            Kt[(col + 0) * FA_W + row] = kv.x;
            Kt[(col + 1) * FA_W + row] = kv.y;
            Kt[(col + 2) * FA_W + row] = kv.z;
            Kt[(col + 3) * FA_W + row] = kv.w;
            float4 vv = *reinterpret_cast<const float4*>(base + (NH + NKV) * HD + col);
            *reinterpret_cast<float4*>(&Vs[row * FA_W + col]) = vv;
        }
        __syncthreads();

        float s[4][4];
#pragma unroll
        for (int i = 0; i < 4; i++)
#pragma unroll
            for (int j = 0; j < 4; j++) s[i][j] = 0.f;

#pragma unroll 8
        for (int d = 0; d < 64; d++) {
            float4 a = *reinterpret_cast<const float4*>(&Qt[d * FA_W + ty * 4]);
            float4 b = *reinterpret_cast<const float4*>(&Kt[d * FA_W + tx * 4]);
            float av[4] = {a.x, a.y, a.z, a.w};
            float bv[4] = {b.x, b.y, b.z, b.w};
#pragma unroll
            for (int i = 0; i < 4; i++)
#pragma unroll
                for (int j = 0; j < 4; j++)
                    s[i][j] += av[i] * bv[j];
        }

#pragma unroll
        for (int i = 0; i < 4; i++)
#pragma unroll
            for (int j = 0; j < 4; j++) s[i][j] *= SCALE;

        if (jt == qt) {
#pragma unroll
            for (int i = 0; i < 4; i++) {
                int gi = ty * 4 + i;
#pragma unroll
                for (int j = 0; j < 4; j++)
                    if (tx * 4 + j > gi) s[i][j] = -1e30f;
            }
        }

#pragma unroll
        for (int i = 0; i < 4; i++) {
            float rm = fmaxf(fmaxf(s[i][0], s[i][1]), fmaxf(s[i][2], s[i][3]));
#pragma unroll
            for (int off = 8; off > 0; off >>= 1)
                rm = fmaxf(rm, __shfl_xor_sync(0xffffffffu, rm, off, 16));
            float mn = fmaxf(m[i], rm);
            float sc = __expf(m[i] - mn);
            float rs = 0.f;
#pragma unroll
            for (int j = 0; j < 4; j++) {
                float pv = __expf(s[i][j] - mn);
                s[i][j] = pv;
                rs += pv;
            }
#pragma unroll
            for (int off = 8; off > 0; off >>= 1)
                rs += __shfl_xor_sync(0xffffffffu, rs, off, 16);
            l[i] = l[i] * sc + rs;
            m[i] = mn;
#pragma unroll
            for (int j = 0; j < 4; j++) o[i][j] *= sc;
        }

#pragma unroll
        for (int j = 0; j < 4; j++) {
            float4 v = make_float4(s[0][j], s[1][j], s[2][j], s[3][j]);
            *reinterpret_cast<float4*>(&Pt[(tx * 4 + j) * FA_W + ty * 4]) = v;
        }
        __syncthreads();

#pragma unroll 8
        for (int j = 0; j < 64; j++) {
            float4 a = *reinterpret_cast<const float4*>(&Pt[j * FA_W + ty * 4]);
            float4 b = *reinterpret_cast<const float4*>(&Vs[j * FA_W + tx * 4]);
            float av[4] = {a.x, a.y, a.z, a.w};
            float bv[4] = {b.x, b.y, b.z, b.w};
#pragma unroll
            for (int i = 0; i < 4; i++)
#pragma unroll
                for (int j2 = 0; j2 < 4; j2++)
                    o[i][j2] += av[i] * bv[j2];
        }
    }

#pragma unroll
    for (int i = 0; i < 4; i++) {
        float inv = 1.f / l[i];
        int row = q0 + ty * 4 + i;
        float4 v = make_float4(o[i][0] * inv, o[i][1] * inv,
                               o[i][2] * inv, o[i][3] * inv);
        *reinterpret_cast<float4*>(&Y[(size_t)row * H_DIM + h * HD + tx * 4]) = v;
    }
}

// ---------------------------------------------------------------------------
// kernel_launch
// ---------------------------------------------------------------------------
extern "C" void kernel_launch(void* const* d_in, const int* in_sizes, int n_in,
                              void* d_out, int out_size)
{
    const float* x    = (const float*)d_in[0];
    const float* fc   = (const float*)d_in[1];
    const float* Wqkv = (const float*)d_in[3];
    const float* Wo   = (const float*)d_in[4];
    float* out = (float*)d_out;

    float* qkv_buf = nullptr;
    float* y_buf   = nullptr;
    __nv_bfloat16 *ahi, *alo, *bhi, *blo;
    cudaGetSymbolAddress((void**)&qkv_buf, g_qkv);
    cudaGetSymbolAddress((void**)&y_buf,   g_y);
    cudaGetSymbolAddress((void**)&ahi, g_ahi);
    cudaGetSymbolAddress((void**)&alo, g_alo);
    cudaGetSymbolAddress((void**)&bhi, g_bhi);
    cudaGetSymbolAddress((void**)&blo, g_blo);

    const size_t fa_smem = (size_t)4 * 64 * FA_W * sizeof(float);
    cudaFuncSetAttribute(flash_kernel,
                         cudaFuncAttributeMaxDynamicSharedMemorySize, (int)fa_smem);
    cudaFuncSetAttribute(hmma_gemm_kernel,
                         cudaFuncAttributeMaxDynamicSharedMemorySize, HM_SMEM);

    // 1) split x and Wqkv into bf16 hi/lo
    {
        int n4 = S_LEN * H_DIM / 4;
        cvt_split_kernel<<<n4 / 256, 256>>>((const float4*)x, (uint2*)ahi, (uint2*)alo, n4);
        int m4 = QKV_COLS * H_DIM / 4;
        cvt_split_kernel<<<m4 / 256, 256>>>((const float4*)Wqkv, (uint2*)bhi, (uint2*)blo, m4);
    }

    // 2) QKV projection (HMMA): g_qkv = x @ Wqkv^T
    {
        dim3 grid(QKV_COLS / 128, S_LEN / 128);
        hmma_gemm_kernel<<<grid, 256, HM_SMEM>>>(ahi, alo, bhi, blo, qkv_buf,
                                                 S_LEN, QKV_COLS, H_DIM);
    }

    // 3) RoPE on q and k in-place
    {
        int total = S_LEN * (NH + NKV) * (HD / 2);
        rope_kernel<<<(total + 255) / 256, 256>>>(qkv_buf, fc);
    }

    // 4) causal GQA flash attention -> g_y
    {
        dim3 grid(S_LEN / 64, NH);
        flash_kernel<<<grid, 256, fa_smem>>>(qkv_buf, y_buf);
    }

    // 5) split y and Wo, then output projection: out = y @ Wo^T
    {
        int n4 = S_LEN * H_DIM / 4;
        cvt_split_kernel<<<n4 / 256, 256>>>((const float4*)y_buf, (uint2*)ahi, (uint2*)alo, n4);
        cvt_split_kernel<<<n4 / 256, 256>>>((const float4*)Wo, (uint2*)bhi, (uint2*)blo, n4);
        dim3 grid(H_DIM / 128, S_LEN / 128);
        hmma_gemm_kernel<<<grid, 256, HM_SMEM>>>(ahi, alo, bhi, blo, out,
                                                 S_LEN, H_DIM, H_DIM);
    }
}

// round 4
// speedup vs baseline: 2.2177x; 2.2009x over previous
#include <cuda_runtime.h>
#include <cuda_bf16.h>
#include <cuda_fp16.h>
#include <cstdint>

// Problem constants (fixed by the dataset)
#define S_LEN 2048
#define H_DIM 2048
#define NH    32
#define NKV   8
#define HD    64
#define QKV_COLS ((NH + 2*NKV) * HD)   // 3072

// ---------------------------------------------------------------------------
// Scratch (allocation-free rule: __device__ globals)
// ---------------------------------------------------------------------------
__device__ float g_qkv[(size_t)S_LEN * QKV_COLS];   // 24 MB
__device__ float g_y  [(size_t)S_LEN * H_DIM];      // 16 MB
__device__ __align__(16) __half g_a[(size_t)S_LEN * H_DIM];       // 8 MB
__device__ __align__(16) __half g_b[(size_t)QKV_COLS * H_DIM];    // 12 MB

// ---------------------------------------------------------------------------
// Arch-agnostic PTX helpers (sm_80+ ISA only; tcgen05 is rejected by the
// harness's plain-sm_103 ptxas target)
// ---------------------------------------------------------------------------
__device__ __forceinline__ uint32_t smem_to_u32(const void* p) {
    uint32_t a;
    asm("{ .reg .u64 t; cvta.to.shared.u64 t, %1; cvt.u32.u64 %0, t; }"
        : "=r"(a) : "l"(p));
    return a;
}

__device__ __forceinline__ void cp_async16(uint32_t smem, const void* gptr) {
    asm volatile("cp.async.cg.shared.global [%0], [%1], 16;"
                 :: "r"(smem), "l"(__cvta_generic_to_global(gptr)) : "memory");
}
__device__ __forceinline__ void cp_commit() {
    asm volatile("cp.async.commit_group;" ::: "memory");
}
__device__ __forceinline__ void cp_wait2() {
    asm volatile("cp.async.wait_group 2;" ::: "memory");
}

__device__ __forceinline__ void ldsm4(uint32_t* r, uint32_t addr) {
    asm volatile("ldmatrix.sync.aligned.m8n8.x4.shared.b16 {%0,%1,%2,%3}, [%4];"
                 : "=r"(r[0]), "=r"(r[1]), "=r"(r[2]), "=r"(r[3]) : "r"(addr));
}

__device__ __forceinline__ void mma16816f16(float* c, const uint32_t* a, const uint32_t* b) {
    asm volatile(
        "mma.sync.aligned.m16n8k16.row.col.f32.f16.f16.f32 "
        "{%0,%1,%2,%3}, {%4,%5,%6,%7}, {%8,%9}, {%0,%1,%2,%3};"
        : "+f"(c[0]), "+f"(c[1]), "+f"(c[2]), "+f"(c[3])
        : "r"(a[0]), "r"(a[1]), "r"(a[2]), "r"(a[3]), "r"(b[0]), "r"(b[1]));
}

// ---------------------------------------------------------------------------
// fp32 -> fp16 convert, vectorized by 4
// ---------------------------------------------------------------------------
__global__ __launch_bounds__(256) void cvt_f16_kernel(
    const float4* __restrict__ in, uint2* __restrict__ out, int n4)
{
    int i = blockIdx.x * blockDim.x + threadIdx.x;
    if (i >= n4) return;
    float4 f = in[i];
    __half2 h01 = __floats2half2_rn(f.x, f.y);
    __half2 h23 = __floats2half2_rn(f.z, f.w);
    out[i] = make_uint2(*reinterpret_cast<uint32_t*>(&h01),
                        *reinterpret_cast<uint32_t*>(&h23));
}

// ---------------------------------------------------------------------------
// HMMA TN GEMM, fp16 in / fp32 out:  C[m][n] = sum_k A[m][k] * B[n][k]
// CTA 128x128, BK=32, 4-stage cp.async pipeline, one barrier per chunk.
// 8 warps: warpM = w>>1 (4), warpN = w&1 (2); warp tile 32(M) x 64(N).
// smem rows padded to 40 halves (80B) -> conflict-free ldmatrix.
// ---------------------------------------------------------------------------
#define HM_BK     32
#define HM_ROWB   80                         // padded row bytes (40 halves)
#define HM_TILE_B (128 * HM_ROWB)            // 10240 B per operand tile
#define HM_STAGE  (2 * HM_TILE_B)            // A + B = 20480 B
#define HM_NSTG   4
#define HM_SMEM   (HM_NSTG * HM_STAGE)       // 81920 B

__global__ __launch_bounds__(256, 2) void hgemm_kernel(
    const __half* __restrict__ A, const __half* __restrict__ B,
    float* __restrict__ C, int M, int N, int K)
{
    extern __shared__ char smem[];
    const uint32_t sbase = smem_to_u32(smem);

    const int tid  = threadIdx.x;
    const int wid  = tid >> 5;
    const int lane = tid & 31;
    const int warpM = wid >> 1;         // 0..3
    const int warpN = wid & 1;          // 0..1
    const int bm = blockIdx.y * 128;
    const int bn = blockIdx.x * 128;

    // cp.async geometry: each thread loads 2 rows per tile (16B chunk each)
    const int ldrow = tid >> 2;         // 0..63
    const int ldc   = (tid & 3) * 16;   // byte chunk within 64B row payload
    const __half* gA0 = A + (size_t)(bm + ldrow) * K + (ldc >> 1);
    const __half* gB0 = B + (size_t)(bn + ldrow) * K + (ldc >> 1);

    // ldmatrix bases (byte offsets within a tile)
    // A x4: lanes 0-7 rows0-7@kLo, 8-15 rows8-15@kLo, 16-23 rows0-7@kHi, 24-31 rows8-15@kHi
    const uint32_t aAddrBase =
        (uint32_t)(warpM * 32 + (lane & 15)) * HM_ROWB + (lane >> 4) * 16;
    // B x4 covers an n-pair (two 8-row n-tiles):
    //   m0: tile0@kLo, m1: tile0@kHi, m2: tile1@kLo, m3: tile1@kHi
    const uint32_t bAddrBase =
        (uint32_t)(warpN * 64 + ((lane >> 4) & 1) * 8 + (lane & 7)) * HM_ROWB
        + ((lane >> 3) & 1) * 16;

    float acc[2][8][4];
#pragma unroll
    for (int m = 0; m < 2; m++)
#pragma unroll
        for (int n = 0; n < 8; n++)
#pragma unroll
            for (int q = 0; q < 4; q++) acc[m][n][q] = 0.f;

    const int nchunk = K / HM_BK;

    auto load_stage = [&](int s, int c) {
        const uint32_t st = sbase + s * HM_STAGE;
        const int k0 = c * HM_BK;
        cp_async16(st + (uint32_t)ldrow * HM_ROWB + ldc, gA0 + k0);
        cp_async16(st + (uint32_t)(ldrow + 64) * HM_ROWB + ldc, gA0 + (size_t)64 * K + k0);
        cp_async16(st + HM_TILE_B + (uint32_t)ldrow * HM_ROWB + ldc, gB0 + k0);
        cp_async16(st + HM_TILE_B + (uint32_t)(ldrow + 64) * HM_ROWB + ldc, gB0 + (size_t)64 * K + k0);
    };

    // prologue: 3 stages in flight
    load_stage(0, 0); cp_commit();
    load_stage(1, 1); cp_commit();
    load_stage(2, 2); cp_commit();

    for (int c = 0; c < nchunk; c++) {
        cp_wait2();              // stage c arrived (own-thread groups)
        __syncthreads();         // all threads' pieces of stage c visible;
                                 // also: everyone finished reading stage c-1
        if (c + 3 < nchunk) load_stage((c + 3) & 3, c + 3);
        cp_commit();             // one group per iteration (may be empty)

        const uint32_t st = sbase + (c & 3) * HM_STAGE;
        const uint32_t sA = st + aAddrBase;
        const uint32_t sB = st + HM_TILE_B + bAddrBase;

#pragma unroll
        for (int ks = 0; ks < 2; ks++) {
            const uint32_t ko = ks * 32;      // 16 halves = 32 bytes
            uint32_t a[2][4];
            ldsm4(a[0], sA + ko);
            ldsm4(a[1], sA + 16 * HM_ROWB + ko);
#pragma unroll
            for (int p = 0; p < 4; p++) {
                uint32_t b[4];
                ldsm4(b, sB + (uint32_t)p * 16 * HM_ROWB + ko);
#pragma unroll
                for (int m = 0; m < 2; m++) {
                    mma16816f16(acc[m][2 * p + 0], a[m], b + 0);
                    mma16816f16(acc[m][2 * p + 1], a[m], b + 2);
                }
            }
        }
    }

    // epilogue: fragment -> global (float2 stores)
    const int qrow = lane >> 2;
    const int qcol = (lane & 3) * 2;
#pragma unroll
    for (int m = 0; m < 2; m++) {
        const int row0 = bm + warpM * 32 + m * 16 + qrow;
#pragma unroll
        for (int n = 0; n < 8; n++) {
            const int col = bn + warpN * 64 + n * 8 + qcol;
            *reinterpret_cast<float2*>(C + (size_t)row0 * N + col) =
                make_float2(acc[m][n][0], acc[m][n][1]);
            *reinterpret_cast<float2*>(C + (size_t)(row0 + 8) * N + col) =
                make_float2(acc[m][n][2], acc[m][n][3]);
        }
    }
}

// ---------------------------------------------------------------------------
// RoPE, interleaved pairing (matches reference apply_rope exactly)
// ---------------------------------------------------------------------------
__global__ __launch_bounds__(256) void rope_kernel(
    float* __restrict__ qkv, const float* __restrict__ fc)
{
    int idx = blockIdx.x * blockDim.x + threadIdx.x;
    int d = idx & 31;
    int h = (idx >> 5) % 40;
    int s = idx / (40 * 32);
    if (s >= S_LEN) return;

    int col = (h < NH) ? h * HD : (NH * HD) + (h - NH) * HD;
    float c  = fc[s * 64 + d * 2 + 0];
    float sn = fc[s * 64 + d * 2 + 1];
    float* p = qkv + (size_t)s * QKV_COLS + col + 2 * d;
    float x0 = p[0], x1 = p[1];
    p[0] = x0 * c - x1 * sn;
    p[1] = x1 * c + x0 * sn;
}

// ---------------------------------------------------------------------------
// FP32 flash attention, causal, GQA (known-good from round 1)
// ---------------------------------------------------------------------------
#define FA_W 68

__global__ __launch_bounds__(256) void flash_kernel(
    const float* __restrict__ qkv, float* __restrict__ Y)
{
    extern __shared__ float sm[];
    float* Qt = sm;
    float* Kt = Qt + 64 * FA_W;
    float* Vs = Kt + 64 * FA_W;
    float* Pt = Vs + 64 * FA_W;

    const int h  = blockIdx.y;
    const int kh = h >> 2;
    const int qt = blockIdx.x;
    const int q0 = qt * 64;

    const int tid = threadIdx.x;
    const int tx  = tid & 15;
    const int ty  = tid >> 4;

#pragma unroll
    for (int r4 = 0; r4 < 4; r4++) {
        int p   = tid + r4 * 256;
        int row = p >> 4;
        int col = (p & 15) * 4;
        float4 v = *reinterpret_cast<const float4*>(
            qkv + (size_t)(q0 + row) * QKV_COLS + h * HD + col);
        Qt[(col + 0) * FA_W + row] = v.x;
        Qt[(col + 1) * FA_W + row] = v.y;
        Qt[(col + 2) * FA_W + row] = v.z;
        Qt[(col + 3) * FA_W + row] = v.w;
    }

    float m[4], l[4], o[4][4];
#pragma unroll
    for (int i = 0; i < 4; i++) {
        m[i] = -1e30f; l[i] = 0.f;
#pragma unroll
        for (int j = 0; j < 4; j++) o[i][j] = 0.f;
    }

    const float SCALE = 0.125f;

    for (int jt = 0; jt <= qt; jt++) {
        const int j0 = jt * 64;
        __syncthreads();

#pragma unroll
        for (int r4 = 0; r4 < 4; r4++) {
            int p   = tid + r4 * 256;
            int row = p >> 4;
            int col = (p & 15) * 4;
            const float* base = qkv + (size_t)(j0 + row) * QKV_COLS + kh * HD;
            float4 kv = *reinterpret_cast<const float4*>(base + NH * HD + col);
            Kt[(col + 0) * FA_W + row] = kv.x;
            Kt[(col + 1) * FA_W + row] = kv.y;
            Kt[(col + 2) * FA_W + row] = kv.z;
            Kt[(col + 3) * FA_W + row] = kv.w;
            float4 vv = *reinterpret_cast<const float4*>(base + (NH + NKV) * HD + col);
            *reinterpret_cast<float4*>(&Vs[row * FA_W + col]) = vv;
        }
        __syncthreads();

        float s[4][4];
#pragma unroll
        for (int i = 0; i < 4; i++)
#pragma unroll
            for (int j = 0; j < 4; j++) s[i][j] = 0.f;

#pragma unroll 8
        for (int d = 0; d < 64; d++) {
            float4 a = *reinterpret_cast<const float4*>(&Qt[d * FA_W + ty * 4]);
            float4 b = *reinterpret_cast<const float4*>(&Kt[d * FA_W + tx * 4]);
            float av[4] = {a.x, a.y, a.z, a.w};
            float bv[4] = {b.x, b.y, b.z, b.w};
#pragma unroll
            for (int i = 0; i < 4; i++)
#pragma unroll
                for (int j = 0; j < 4; j++)
                    s[i][j] += av[i] * bv[j];
        }

#pragma unroll
        for (int i = 0; i < 4; i++)
#pragma unroll
            for (int j = 0; j < 4; j++) s[i][j] *= SCALE;

        if (jt == qt) {
#pragma unroll
            for (int i = 0; i < 4; i++) {
                int gi = ty * 4 + i;
#pragma unroll
                for (int j = 0; j < 4; j++)
                    if (tx * 4 + j > gi) s[i][j] = -1e30f;
            }
        }

#pragma unroll
        for (int i = 0; i < 4; i++) {
            float rm = fmaxf(fmaxf(s[i][0], s[i][1]), fmaxf(s[i][2], s[i][3]));
#pragma unroll
            for (int off = 8; off > 0; off >>= 1)
                rm = fmaxf(rm, __shfl_xor_sync(0xffffffffu, rm, off, 16));
            float mn = fmaxf(m[i], rm);
            float sc = __expf(m[i] - mn);
            float rs = 0.f;
#pragma unroll
            for (int j = 0; j < 4; j++) {
                float pv = __expf(s[i][j] - mn);
                s[i][j] = pv;
                rs += pv;
            }
#pragma unroll
            for (int off = 8; off > 0; off >>= 1)
                rs += __shfl_xor_sync(0xffffffffu, rs, off, 16);
            l[i] = l[i] * sc + rs;
            m[i] = mn;
#pragma unroll
            for (int j = 0; j < 4; j++) o[i][j] *= sc;
        }

#pragma unroll
        for (int j = 0; j < 4; j++) {
            float4 v = make_float4(s[0][j], s[1][j], s[2][j], s[3][j]);
            *reinterpret_cast<float4*>(&Pt[(tx * 4 + j) * FA_W + ty * 4]) = v;
        }
        __syncthreads();

#pragma unroll 8
        for (int j = 0; j < 64; j++) {
            float4 a = *reinterpret_cast<const float4*>(&Pt[j * FA_W + ty * 4]);
            float4 b = *reinterpret_cast<const float4*>(&Vs[j * FA_W + tx * 4]);
            float av[4] = {a.x, a.y, a.z, a.w};
            float bv[4] = {b.x, b.y, b.z, b.w};
#pragma unroll
            for (int i = 0; i < 4; i++)
#pragma unroll
                for (int j2 = 0; j2 < 4; j2++)
                    o[i][j2] += av[i] * bv[j2];
        }
    }

#pragma unroll
    for (int i = 0; i < 4; i++) {
        float inv = 1.f / l[i];
        int row = q0 + ty * 4 + i;
        float4 v = make_float4(o[i][0] * inv, o[i][1] * inv,
                               o[i][2] * inv, o[i][3] * inv);
        *reinterpret_cast<float4*>(&Y[(size_t)row * H_DIM + h * HD + tx * 4]) = v;
    }
}

// ---------------------------------------------------------------------------
// kernel_launch
// ---------------------------------------------------------------------------
extern "C" void kernel_launch(void* const* d_in, const int* in_sizes, int n_in,
                              void* d_out, int out_size)
{
    const float* x    = (const float*)d_in[0];
    const float* fc   = (const float*)d_in[1];
    const float* Wqkv = (const float*)d_in[3];
    const float* Wo   = (const float*)d_in[4];
    float* out = (float*)d_out;

    float* qkv_buf = nullptr;
    float* y_buf   = nullptr;
    __half *ga, *gb;
    cudaGetSymbolAddress((void**)&qkv_buf, g_qkv);
    cudaGetSymbolAddress((void**)&y_buf,   g_y);
    cudaGetSymbolAddress((void**)&ga, g_a);
    cudaGetSymbolAddress((void**)&gb, g_b);

    const size_t fa_smem = (size_t)4 * 64 * FA_W * sizeof(float);
    cudaFuncSetAttribute(flash_kernel,
                         cudaFuncAttributeMaxDynamicSharedMemorySize, (int)fa_smem);
    cudaFuncSetAttribute(hgemm_kernel,
                         cudaFuncAttributeMaxDynamicSharedMemorySize, HM_SMEM);

    // 1) convert x and Wqkv to fp16
    {
        int n4 = S_LEN * H_DIM / 4;
        cvt_f16_kernel<<<n4 / 256, 256>>>((const float4*)x, (uint2*)ga, n4);
        int m4 = QKV_COLS * H_DIM / 4;
        cvt_f16_kernel<<<m4 / 256, 256>>>((const float4*)Wqkv, (uint2*)gb, m4);
    }

    // 2) QKV projection (HMMA fp16): g_qkv = x @ Wqkv^T
    {
        dim3 grid(QKV_COLS / 128, S_LEN / 128);
        hgemm_kernel<<<grid, 256, HM_SMEM>>>(ga, gb, qkv_buf, S_LEN, QKV_COLS, H_DIM);
    }

    // 3) RoPE on q and k in-place
    {
        int total = S_LEN * (NH + NKV) * (HD / 2);
        rope_kernel<<<(total + 255) / 256, 256>>>(qkv_buf, fc);
    }

    // 4) causal GQA flash attention -> g_y
    {
        dim3 grid(S_LEN / 64, NH);
        flash_kernel<<<grid, 256, fa_smem>>>(qkv_buf, y_buf);
    }

    // 5) convert y and Wo to fp16, then output projection: out = y @ Wo^T
    {
        int n4 = S_LEN * H_DIM / 4;
        cvt_f16_kernel<<<n4 / 256, 256>>>((const float4*)y_buf, (uint2*)ga, n4);
        cvt_f16_kernel<<<n4 / 256, 256>>>((const float4*)Wo, (uint2*)gb, n4);
        dim3 grid(H_DIM / 128, S_LEN / 128);
        hgemm_kernel<<<grid, 256, HM_SMEM>>>(ga, gb, out, S_LEN, H_DIM, H_DIM);
    }
}

// round 5
// speedup vs baseline: 6.3224x; 2.8508x over previous
#include <cuda_runtime.h>
#include <cuda_fp16.h>
#include <cstdint>

// Problem constants (fixed by the dataset)
#define S_LEN 2048
#define H_DIM 2048
#define NH    32
#define NKV   8
#define HD    64
#define QKV_COLS ((NH + 2*NKV) * HD)   // 3072

// ---------------------------------------------------------------------------
// Scratch (allocation-free rule: __device__ globals)
// ---------------------------------------------------------------------------
__device__ float g_qkv[(size_t)S_LEN * QKV_COLS];                 // 24 MB fp32
__device__ __align__(16) __half g_qkvh[(size_t)S_LEN * QKV_COLS]; // 12 MB fp16
__device__ __align__(16) __half g_a[(size_t)S_LEN * H_DIM];       // 8 MB
__device__ __align__(16) __half g_b[(size_t)QKV_COLS * H_DIM];    // 12 MB

// ---------------------------------------------------------------------------
// Arch-agnostic PTX helpers (sm_80+ ISA; tcgen05 rejected by plain-sm_103 ptxas)
// ---------------------------------------------------------------------------
__device__ __forceinline__ uint32_t smem_to_u32(const void* p) {
    uint32_t a;
    asm("{ .reg .u64 t; cvta.to.shared.u64 t, %1; cvt.u32.u64 %0, t; }"
        : "=r"(a) : "l"(p));
    return a;
}
__device__ __forceinline__ void cp_async16(uint32_t smem, const void* gptr) {
    asm volatile("cp.async.cg.shared.global [%0], [%1], 16;"
                 :: "r"(smem), "l"(__cvta_generic_to_global(gptr)) : "memory");
}
__device__ __forceinline__ void cp_commit() {
    asm volatile("cp.async.commit_group;" ::: "memory");
}
__device__ __forceinline__ void cp_wait1() {
    asm volatile("cp.async.wait_group 1;" ::: "memory");
}
__device__ __forceinline__ void cp_wait2() {
    asm volatile("cp.async.wait_group 2;" ::: "memory");
}
__device__ __forceinline__ void ldsm4(uint32_t* r, uint32_t addr) {
    asm volatile("ldmatrix.sync.aligned.m8n8.x4.shared.b16 {%0,%1,%2,%3}, [%4];"
                 : "=r"(r[0]), "=r"(r[1]), "=r"(r[2]), "=r"(r[3]) : "r"(addr));
}
__device__ __forceinline__ void ldsm4t(uint32_t* r, uint32_t addr) {
    asm volatile("ldmatrix.sync.aligned.m8n8.x4.trans.shared.b16 {%0,%1,%2,%3}, [%4];"
                 : "=r"(r[0]), "=r"(r[1]), "=r"(r[2]), "=r"(r[3]) : "r"(addr));
}
__device__ __forceinline__ void mma16816f16(float* c, const uint32_t* a, const uint32_t* b) {
    asm volatile(
        "mma.sync.aligned.m16n8k16.row.col.f32.f16.f16.f32 "
        "{%0,%1,%2,%3}, {%4,%5,%6,%7}, {%8,%9}, {%0,%1,%2,%3};"
        : "+f"(c[0]), "+f"(c[1]), "+f"(c[2]), "+f"(c[3])
        : "r"(a[0]), "r"(a[1]), "r"(a[2]), "r"(a[3]), "r"(b[0]), "r"(b[1]));
}
__device__ __forceinline__ uint32_t pack_h2(float a, float b) {
    __half2 h = __floats2half2_rn(a, b);
    return *reinterpret_cast<uint32_t*>(&h);
}

// Fast 2^d on the FMA pipe (d <= 0; clamped). ~1e-6 rel accuracy.
__device__ __forceinline__ float fexp2(float d) {
    d = fmaxf(d, -80.0f);
    float t  = d + 12582912.0f;                 // round-to-int via magic
    float nf = t - 12582912.0f;
    float f  = d - nf;                          // f in [-0.5, 0.5]
    int   n  = __float_as_int(t) - 0x4B400000;
    float p  = 1.3333558146e-3f;
    p = fmaf(p, f, 9.6181291e-3f);
    p = fmaf(p, f, 5.5504108664e-2f);
    p = fmaf(p, f, 2.4022650696e-1f);
    p = fmaf(p, f, 6.9314718056e-1f);
    p = fmaf(p, f, 1.0f);
    return __int_as_float(__float_as_int(p) + (n << 23));
}

// ---------------------------------------------------------------------------
// fp32 -> fp16 convert, vectorized by 4
// ---------------------------------------------------------------------------
__global__ __launch_bounds__(256) void cvt_f16_kernel(
    const float4* __restrict__ in, uint2* __restrict__ out, int n4)
{
    int i = blockIdx.x * blockDim.x + threadIdx.x;
    if (i >= n4) return;
    float4 f = in[i];
    out[i] = make_uint2(pack_h2(f.x, f.y), pack_h2(f.z, f.w));
}

// ---------------------------------------------------------------------------
// HMMA TN GEMM, fp16 in / fp32 out (unchanged from round 4 — validated)
// ---------------------------------------------------------------------------
#define HM_ROWB   80
#define HM_TILE_B (128 * HM_ROWB)
#define HM_STAGE  (2 * HM_TILE_B)
#define HM_SMEM   (4 * HM_STAGE)

__global__ __launch_bounds__(256, 2) void hgemm_kernel(
    const __half* __restrict__ A, const __half* __restrict__ B,
    float* __restrict__ C, int M, int N, int K)
{
    extern __shared__ char smem[];
    const uint32_t sbase = smem_to_u32(smem);

    const int tid  = threadIdx.x;
    const int wid  = tid >> 5;
    const int lane = tid & 31;
    const int warpM = wid >> 1;
    const int warpN = wid & 1;
    const int bm = blockIdx.y * 128;
    const int bn = blockIdx.x * 128;

    const int ldrow = tid >> 2;
    const int ldc   = (tid & 3) * 16;
    const __half* gA0 = A + (size_t)(bm + ldrow) * K + (ldc >> 1);
    const __half* gB0 = B + (size_t)(bn + ldrow) * K + (ldc >> 1);

    const uint32_t aAddrBase =
        (uint32_t)(warpM * 32 + (lane & 15)) * HM_ROWB + (lane >> 4) * 16;
    const uint32_t bAddrBase =
        (uint32_t)(warpN * 64 + ((lane >> 4) & 1) * 8 + (lane & 7)) * HM_ROWB
        + ((lane >> 3) & 1) * 16;

    float acc[2][8][4];
#pragma unroll
    for (int m = 0; m < 2; m++)
#pragma unroll
        for (int n = 0; n < 8; n++)
#pragma unroll
            for (int q = 0; q < 4; q++) acc[m][n][q] = 0.f;

    const int nchunk = K / 32;

    auto load_stage = [&](int s, int c) {
        const uint32_t st = sbase + s * HM_STAGE;
        const int k0 = c * 32;
        cp_async16(st + (uint32_t)ldrow * HM_ROWB + ldc, gA0 + k0);
        cp_async16(st + (uint32_t)(ldrow + 64) * HM_ROWB + ldc, gA0 + (size_t)64 * K + k0);
        cp_async16(st + HM_TILE_B + (uint32_t)ldrow * HM_ROWB + ldc, gB0 + k0);
        cp_async16(st + HM_TILE_B + (uint32_t)(ldrow + 64) * HM_ROWB + ldc, gB0 + (size_t)64 * K + k0);
    };

    load_stage(0, 0); cp_commit();
    load_stage(1, 1); cp_commit();
    load_stage(2, 2); cp_commit();

    for (int c = 0; c < nchunk; c++) {
        cp_wait2();
        __syncthreads();
        if (c + 3 < nchunk) load_stage((c + 3) & 3, c + 3);
        cp_commit();

        const uint32_t st = sbase + (c & 3) * HM_STAGE;
        const uint32_t sA = st + aAddrBase;
        const uint32_t sB = st + HM_TILE_B + bAddrBase;

#pragma unroll
        for (int ks = 0; ks < 2; ks++) {
            const uint32_t ko = ks * 32;
            uint32_t a[2][4];
            ldsm4(a[0], sA + ko);
            ldsm4(a[1], sA + 16 * HM_ROWB + ko);
#pragma unroll
            for (int p = 0; p < 4; p++) {
                uint32_t b[4];
                ldsm4(b, sB + (uint32_t)p * 16 * HM_ROWB + ko);
#pragma unroll
                for (int m = 0; m < 2; m++) {
                    mma16816f16(acc[m][2 * p + 0], a[m], b + 0);
                    mma16816f16(acc[m][2 * p + 1], a[m], b + 2);
                }
            }
        }
    }

    const int qrow = lane >> 2;
    const int qcol = (lane & 3) * 2;
#pragma unroll
    for (int m = 0; m < 2; m++) {
        const int row0 = bm + warpM * 32 + m * 16 + qrow;
#pragma unroll
        for (int n = 0; n < 8; n++) {
            const int col = bn + warpN * 64 + n * 8 + qcol;
            *reinterpret_cast<float2*>(C + (size_t)row0 * N + col) =
                make_float2(acc[m][n][0], acc[m][n][1]);
            *reinterpret_cast<float2*>(C + (size_t)(row0 + 8) * N + col) =
                make_float2(acc[m][n][2], acc[m][n][3]);
        }
    }
}

// ---------------------------------------------------------------------------
// RoPE (interleaved, matches reference) + fp16 conversion of all of QKV.
// Slots 0..31 = q heads, 32..39 = k heads (rotate); 40..47 = v heads (convert).
// ---------------------------------------------------------------------------
__global__ __launch_bounds__(256) void rope_cvt_kernel(
    const float* __restrict__ qkv, const float* __restrict__ fc,
    __half* __restrict__ out)
{
    int idx = blockIdx.x * blockDim.x + threadIdx.x;
    int d    = idx & 31;
    int slot = (idx >> 5) % 48;
    int s    = idx / (48 * 32);
    if (s >= S_LEN) return;

    const float* p = qkv + (size_t)s * QKV_COLS + slot * 64 + 2 * d;
    float x0 = p[0], x1 = p[1];
    if (slot < 40) {
        float c  = fc[s * 64 + d * 2 + 0];
        float sn = fc[s * 64 + d * 2 + 1];
        float t0 = x0 * c - x1 * sn;
        float t1 = x1 * c + x0 * sn;
        x0 = t0; x1 = t1;
    }
    __half2 h = __floats2half2_rn(x0, x1);
    *reinterpret_cast<__half2*>(out + (size_t)s * QKV_COLS + slot * 64 + 2 * d) = h;
}

// ---------------------------------------------------------------------------
// HMMA flash attention, causal, GQA. fp16 QK^T / PV on tensor pipe, fp32
// online softmax in log2 domain with FMA-pipe exp2. Output written as fp16.
// Block: (q-tile of 64 rows, head). 4 warps; warp owns 16 full rows (FA-2).
// smem: Q[64][72h] + 2 stages x (K + V)[64][72h], 144B-pitch rows.
// ---------------------------------------------------------------------------
#define FK_ROW  144
#define FK_TILE (64 * FK_ROW)                 // 9216 B
#define FK_SMEM (FK_TILE + 2 * 2 * FK_TILE)   // Q + 2 stages * (K,V) = 46080

__global__ __launch_bounds__(128) void flash_hmma_kernel(
    const __half* __restrict__ qkvh, __half* __restrict__ Y)
{
    extern __shared__ char sm[];
    const uint32_t sb = smem_to_u32(sm);

    const int h  = blockIdx.y;
    const int kh = h >> 2;
    const int qt = blockIdx.x;
    const int q0 = qt * 64;

    const int tid  = threadIdx.x;
    const int w    = tid >> 5;
    const int lane = tid & 31;

    // exp2 scale: (1/sqrt(64)) * log2(e)
    const float C2 = 0.18033688011112042f;

    // ldmatrix address bases
    const uint32_t qAddr = (uint32_t)(w * 16 + (lane & 15)) * FK_ROW + (lane >> 4) * 16;
    const uint32_t kAddr = (uint32_t)(((lane >> 4) & 1) * 8 + (lane & 7)) * FK_ROW
                           + ((lane >> 3) & 1) * 16;
    const uint32_t vAddr = (uint32_t)((lane & 7) + ((lane >> 3) & 1) * 8) * FK_ROW
                           + (lane >> 4) * 16;

    // cp.async loaders: 64 rows x 128B, 4 chunks per thread
    auto load_q = [&]() {
#pragma unroll
        for (int i = 0; i < 4; i++) {
            int p = tid + i * 128, row = p >> 3, ch = p & 7;
            cp_async16(sb + (uint32_t)row * FK_ROW + ch * 16,
                       qkvh + (size_t)(q0 + row) * QKV_COLS + h * HD + ch * 8);
        }
    };
    auto load_kv = [&](int s, int jt) {
        const int j0 = jt * 64;
        const uint32_t Kb = sb + FK_TILE + s * 2 * FK_TILE;
#pragma unroll
        for (int i = 0; i < 4; i++) {
            int p = tid + i * 128, row = p >> 3, ch = p & 7;
            const __half* base = qkvh + (size_t)(j0 + row) * QKV_COLS + kh * HD + ch * 8;
            cp_async16(Kb + (uint32_t)row * FK_ROW + ch * 16, base + NH * HD);
            cp_async16(Kb + FK_TILE + (uint32_t)row * FK_ROW + ch * 16, base + (NH + NKV) * HD);
        }
    };

    // prologue
    load_q(); load_kv(0, 0); cp_commit();
    if (qt >= 1) load_kv(1, 1);
    cp_commit();

    uint32_t aQ[4][4];
    float o[8][4];
#pragma unroll
    for (int n = 0; n < 8; n++)
#pragma unroll
        for (int q = 0; q < 4; q++) o[n][q] = 0.f;
    float m2[2] = { -1e30f, -1e30f };
    float l[2]  = { 0.f, 0.f };

    for (int jt = 0; jt <= qt; jt++) {
        cp_wait1();
        __syncthreads();
        if (jt == 0) {
#pragma unroll
            for (int kc = 0; kc < 4; kc++) ldsm4(aQ[kc], sb + qAddr + kc * 32);
        }

        const uint32_t Kb = sb + FK_TILE + (jt & 1) * 2 * FK_TILE;
        const uint32_t Vb = Kb + FK_TILE;

        // --- scores: 64 rows (16/warp) x 64 kv ---
        float sc[8][4];
#pragma unroll
        for (int n = 0; n < 8; n++)
#pragma unroll
            for (int q = 0; q < 4; q++) sc[n][q] = 0.f;
#pragma unroll
        for (int p = 0; p < 4; p++) {
#pragma unroll
            for (int kc = 0; kc < 4; kc++) {
                uint32_t b[4];
                ldsm4(b, Kb + kAddr + (uint32_t)p * 16 * FK_ROW + kc * 32);
                mma16816f16(sc[2 * p + 0], aQ[kc], b + 0);
                mma16816f16(sc[2 * p + 1], aQ[kc], b + 2);
            }
        }

        // --- causal mask (diagonal tile only) ---
        if (jt == qt) {
            const int r0 = w * 16 + (lane >> 2);
            const int cb = (lane & 3) * 2;
#pragma unroll
            for (int n = 0; n < 8; n++) {
#pragma unroll
                for (int e = 0; e < 2; e++) {
                    int cl = n * 8 + cb + e;
                    if (cl > r0)     sc[n][e]     = -1e30f;
                    if (cl > r0 + 8) sc[n][e + 2] = -1e30f;
                }
            }
        }

        // --- online softmax (log2 domain), warp-local rows ---
        uint32_t ph[8][2];
#pragma unroll
        for (int i = 0; i < 2; i++) {
            float mr = -1e30f;
#pragma unroll
            for (int n = 0; n < 8; n++)
                mr = fmaxf(mr, fmaxf(sc[n][2 * i], sc[n][2 * i + 1]));
            mr = fmaxf(mr, __shfl_xor_sync(0xffffffffu, mr, 1));
            mr = fmaxf(mr, __shfl_xor_sync(0xffffffffu, mr, 2));
            float m2n = fmaxf(m2[i], mr * C2);
            float r = fexp2(m2[i] - m2n);
            m2[i] = m2n;
            float sum = 0.f;
#pragma unroll
            for (int n = 0; n < 8; n++) {
                float p0 = fexp2(fmaf(sc[n][2 * i],     C2, -m2n));
                float p1 = fexp2(fmaf(sc[n][2 * i + 1], C2, -m2n));
                sum += p0 + p1;
                ph[n][i] = pack_h2(p0, p1);
            }
            sum += __shfl_xor_sync(0xffffffffu, sum, 1);
            sum += __shfl_xor_sync(0xffffffffu, sum, 2);
            l[i] = l[i] * r + sum;
#pragma unroll
            for (int n = 0; n < 8; n++) {
                o[n][2 * i]     *= r;
                o[n][2 * i + 1] *= r;
            }
        }

        // --- O += P @ V ---
#pragma unroll
        for (int kc = 0; kc < 4; kc++) {
            uint32_t a[4] = { ph[2 * kc][0], ph[2 * kc][1],
                              ph[2 * kc + 1][0], ph[2 * kc + 1][1] };
#pragma unroll
            for (int vp = 0; vp < 4; vp++) {
                uint32_t b[4];
                ldsm4t(b, Vb + vAddr + (uint32_t)kc * 16 * FK_ROW + vp * 32);
                mma16816f16(o[2 * vp + 0], a, b + 0);
                mma16816f16(o[2 * vp + 1], a, b + 2);
            }
        }

        __syncthreads();
        if (jt + 2 <= qt) load_kv(jt & 1, jt + 2);
        cp_commit();
    }

    // --- epilogue: fp16 y ---
#pragma unroll
    for (int i = 0; i < 2; i++) {
        float inv = 1.f / l[i];
        int row = q0 + w * 16 + (lane >> 2) + 8 * i;
        __half* yr = Y + (size_t)row * H_DIM + h * HD + (lane & 3) * 2;
#pragma unroll
        for (int n = 0; n < 8; n++) {
            __half2 v = __floats2half2_rn(o[n][2 * i] * inv, o[n][2 * i + 1] * inv);
            *reinterpret_cast<__half2*>(yr + n * 8) = v;
        }
    }
}

// ---------------------------------------------------------------------------
// kernel_launch
// ---------------------------------------------------------------------------
extern "C" void kernel_launch(void* const* d_in, const int* in_sizes, int n_in,
                              void* d_out, int out_size)
{
    const float* x    = (const float*)d_in[0];
    const float* fc   = (const float*)d_in[1];
    const float* Wqkv = (const float*)d_in[3];
    const float* Wo   = (const float*)d_in[4];
    float* out = (float*)d_out;

    float* qkv_buf = nullptr;
    __half *qkvh, *ga, *gb;
    cudaGetSymbolAddress((void**)&qkv_buf, g_qkv);
    cudaGetSymbolAddress((void**)&qkvh, g_qkvh);
    cudaGetSymbolAddress((void**)&ga, g_a);
    cudaGetSymbolAddress((void**)&gb, g_b);

    cudaFuncSetAttribute(hgemm_kernel,
                         cudaFuncAttributeMaxDynamicSharedMemorySize, HM_SMEM);
    cudaFuncSetAttribute(flash_hmma_kernel,
                         cudaFuncAttributeMaxDynamicSharedMemorySize, FK_SMEM);

    // 1) convert x and Wqkv to fp16
    {
        int n4 = S_LEN * H_DIM / 4;
        cvt_f16_kernel<<<n4 / 256, 256>>>((const float4*)x, (uint2*)ga, n4);
        int m4 = QKV_COLS * H_DIM / 4;
        cvt_f16_kernel<<<m4 / 256, 256>>>((const float4*)Wqkv, (uint2*)gb, m4);
    }

    // 2) QKV projection: g_qkv (fp32) = x @ Wqkv^T
    {
        dim3 grid(QKV_COLS / 128, S_LEN / 128);
        hgemm_kernel<<<grid, 256, HM_SMEM>>>(ga, gb, qkv_buf, S_LEN, QKV_COLS, H_DIM);
    }

    // 3) RoPE (fp32) + convert all of qkv to fp16
    {
        int total = S_LEN * 48 * 32;
        rope_cvt_kernel<<<total / 256, 256>>>(qkv_buf, fc, qkvh);
    }

    // 4) convert Wo to fp16 (g_b free after gemm1)
    {
        int n4 = S_LEN * H_DIM / 4;
        cvt_f16_kernel<<<n4 / 256, 256>>>((const float4*)Wo, (uint2*)gb, n4);
    }

    // 5) HMMA flash attention -> g_a (fp16 y)
    {
        dim3 grid(S_LEN / 64, NH);
        flash_hmma_kernel<<<grid, 128, FK_SMEM>>>(qkvh, ga);
    }

    // 6) output projection: out = y @ Wo^T
    {
        dim3 grid(H_DIM / 128, S_LEN / 128);
        hgemm_kernel<<<grid, 256, HM_SMEM>>>(ga, gb, out, S_LEN, H_DIM, H_DIM);
    }
}

// round 6
// speedup vs baseline: 6.3469x; 1.0039x over previous
#include <cuda_runtime.h>
#include <cuda_fp16.h>
#include <cstdint>

// Problem constants (fixed by the dataset)
#define S_LEN 2048
#define H_DIM 2048
#define NH    32
#define NKV   8
#define HD    64
#define QKV_COLS ((NH + 2*NKV) * HD)   // 3072

// ---------------------------------------------------------------------------
// Scratch (allocation-free rule: __device__ globals)
// ---------------------------------------------------------------------------
__device__ __align__(16) __half g_qkvh[(size_t)S_LEN * QKV_COLS]; // 12 MB
__device__ __align__(16) __half g_a[(size_t)S_LEN * H_DIM];       // 8 MB (x, then y)
__device__ __align__(16) __half g_b[(size_t)QKV_COLS * H_DIM];    // 12 MB (Wqkv, then Wo)

// ---------------------------------------------------------------------------
// Arch-agnostic PTX helpers (sm_80+ ISA; tcgen05 rejected by plain-sm_103 ptxas)
// ---------------------------------------------------------------------------
__device__ __forceinline__ uint32_t smem_to_u32(const void* p) {
    uint32_t a;
    asm("{ .reg .u64 t; cvta.to.shared.u64 t, %1; cvt.u32.u64 %0, t; }"
        : "=r"(a) : "l"(p));
    return a;
}
__device__ __forceinline__ void cp_async16(uint32_t smem, const void* gptr) {
    asm volatile("cp.async.cg.shared.global [%0], [%1], 16;"
                 :: "r"(smem), "l"(__cvta_generic_to_global(gptr)) : "memory");
}
__device__ __forceinline__ void cp_commit() {
    asm volatile("cp.async.commit_group;" ::: "memory");
}
__device__ __forceinline__ void cp_wait1() {
    asm volatile("cp.async.wait_group 1;" ::: "memory");
}
__device__ __forceinline__ void cp_wait2() {
    asm volatile("cp.async.wait_group 2;" ::: "memory");
}
__device__ __forceinline__ void ldsm4(uint32_t* r, uint32_t addr) {
    asm volatile("ldmatrix.sync.aligned.m8n8.x4.shared.b16 {%0,%1,%2,%3}, [%4];"
                 : "=r"(r[0]), "=r"(r[1]), "=r"(r[2]), "=r"(r[3]) : "r"(addr));
}
__device__ __forceinline__ void ldsm4t(uint32_t* r, uint32_t addr) {
    asm volatile("ldmatrix.sync.aligned.m8n8.x4.trans.shared.b16 {%0,%1,%2,%3}, [%4];"
                 : "=r"(r[0]), "=r"(r[1]), "=r"(r[2]), "=r"(r[3]) : "r"(addr));
}
__device__ __forceinline__ void mma16816f16(float* c, const uint32_t* a, const uint32_t* b) {
    asm volatile(
        "mma.sync.aligned.m16n8k16.row.col.f32.f16.f16.f32 "
        "{%0,%1,%2,%3}, {%4,%5,%6,%7}, {%8,%9}, {%0,%1,%2,%3};"
        : "+f"(c[0]), "+f"(c[1]), "+f"(c[2]), "+f"(c[3])
        : "r"(a[0]), "r"(a[1]), "r"(a[2]), "r"(a[3]), "r"(b[0]), "r"(b[1]));
}
__device__ __forceinline__ uint32_t pack_h2(float a, float b) {
    __half2 h = __floats2half2_rn(a, b);
    return *reinterpret_cast<uint32_t*>(&h);
}

// Fast 2^d on the FMA pipe (d <= 0; clamped). ~1e-6 rel accuracy.
__device__ __forceinline__ float fexp2(float d) {
    d = fmaxf(d, -80.0f);
    float t  = d + 12582912.0f;
    float nf = t - 12582912.0f;
    float f  = d - nf;
    int   n  = __float_as_int(t) - 0x4B400000;
    float p  = 1.3333558146e-3f;
    p = fmaf(p, f, 9.6181291e-3f);
    p = fmaf(p, f, 5.5504108664e-2f);
    p = fmaf(p, f, 2.4022650696e-1f);
    p = fmaf(p, f, 6.9314718056e-1f);
    p = fmaf(p, f, 1.0f);
    return __int_as_float(__float_as_int(p) + (n << 23));
}

// ---------------------------------------------------------------------------
// fp32 -> fp16 convert, vectorized by 4
// ---------------------------------------------------------------------------
__global__ __launch_bounds__(256) void cvt_f16_kernel(
    const float4* __restrict__ in, uint2* __restrict__ out, int n4)
{
    int i = blockIdx.x * blockDim.x + threadIdx.x;
    if (i >= n4) return;
    float4 f = in[i];
    out[i] = make_uint2(pack_h2(f.x, f.y), pack_h2(f.z, f.w));
}

// ---------------------------------------------------------------------------
// HMMA TN GEMM, fp16 in, templated output (fp32 or fp16).
// CTA 128x128, BK=32, 4-stage cp.async pipeline. (mainloop validated R4/R5)
// ---------------------------------------------------------------------------
#define HM_ROWB   80
#define HM_TILE_B (128 * HM_ROWB)
#define HM_STAGE  (2 * HM_TILE_B)
#define HM_SMEM   (4 * HM_STAGE)

template <bool HALF_OUT>
__global__ __launch_bounds__(256, 2) void hgemm_kernel(
    const __half* __restrict__ A, const __half* __restrict__ B,
    void* __restrict__ Cv, int M, int N, int K)
{
    extern __shared__ char smem[];
    const uint32_t sbase = smem_to_u32(smem);

    const int tid  = threadIdx.x;
    const int wid  = tid >> 5;
    const int lane = tid & 31;
    const int warpM = wid >> 1;
    const int warpN = wid & 1;
    const int bm = blockIdx.y * 128;
    const int bn = blockIdx.x * 128;

    const int ldrow = tid >> 2;
    const int ldc   = (tid & 3) * 16;
    const __half* gA0 = A + (size_t)(bm + ldrow) * K + (ldc >> 1);
    const __half* gB0 = B + (size_t)(bn + ldrow) * K + (ldc >> 1);

    const uint32_t aAddrBase =
        (uint32_t)(warpM * 32 + (lane & 15)) * HM_ROWB + (lane >> 4) * 16;
    const uint32_t bAddrBase =
        (uint32_t)(warpN * 64 + ((lane >> 4) & 1) * 8 + (lane & 7)) * HM_ROWB
        + ((lane >> 3) & 1) * 16;

    float acc[2][8][4];
#pragma unroll
    for (int m = 0; m < 2; m++)
#pragma unroll
        for (int n = 0; n < 8; n++)
#pragma unroll
            for (int q = 0; q < 4; q++) acc[m][n][q] = 0.f;

    const int nchunk = K / 32;

    auto load_stage = [&](int s, int c) {
        const uint32_t st = sbase + s * HM_STAGE;
        const int k0 = c * 32;
        cp_async16(st + (uint32_t)ldrow * HM_ROWB + ldc, gA0 + k0);
        cp_async16(st + (uint32_t)(ldrow + 64) * HM_ROWB + ldc, gA0 + (size_t)64 * K + k0);
        cp_async16(st + HM_TILE_B + (uint32_t)ldrow * HM_ROWB + ldc, gB0 + k0);
        cp_async16(st + HM_TILE_B + (uint32_t)(ldrow + 64) * HM_ROWB + ldc, gB0 + (size_t)64 * K + k0);
    };

    load_stage(0, 0); cp_commit();
    load_stage(1, 1); cp_commit();
    load_stage(2, 2); cp_commit();

    for (int c = 0; c < nchunk; c++) {
        cp_wait2();
        __syncthreads();
        if (c + 3 < nchunk) load_stage((c + 3) & 3, c + 3);
        cp_commit();

        const uint32_t st = sbase + (c & 3) * HM_STAGE;
        const uint32_t sA = st + aAddrBase;
        const uint32_t sB = st + HM_TILE_B + bAddrBase;

#pragma unroll
        for (int ks = 0; ks < 2; ks++) {
            const uint32_t ko = ks * 32;
            uint32_t a[2][4];
            ldsm4(a[0], sA + ko);
            ldsm4(a[1], sA + 16 * HM_ROWB + ko);
#pragma unroll
            for (int p = 0; p < 4; p++) {
                uint32_t b[4];
                ldsm4(b, sB + (uint32_t)p * 16 * HM_ROWB + ko);
#pragma unroll
                for (int m = 0; m < 2; m++) {
                    mma16816f16(acc[m][2 * p + 0], a[m], b + 0);
                    mma16816f16(acc[m][2 * p + 1], a[m], b + 2);
                }
            }
        }
    }

    const int qrow = lane >> 2;
    const int qcol = (lane & 3) * 2;
#pragma unroll
    for (int m = 0; m < 2; m++) {
        const int row0 = bm + warpM * 32 + m * 16 + qrow;
#pragma unroll
        for (int n = 0; n < 8; n++) {
            const int col = bn + warpN * 64 + n * 8 + qcol;
            if (HALF_OUT) {
                __half* C = (__half*)Cv;
                *reinterpret_cast<uint32_t*>(C + (size_t)row0 * N + col) =
                    pack_h2(acc[m][n][0], acc[m][n][1]);
                *reinterpret_cast<uint32_t*>(C + (size_t)(row0 + 8) * N + col) =
                    pack_h2(acc[m][n][2], acc[m][n][3]);
            } else {
                float* C = (float*)Cv;
                *reinterpret_cast<float2*>(C + (size_t)row0 * N + col) =
                    make_float2(acc[m][n][0], acc[m][n][1]);
                *reinterpret_cast<float2*>(C + (size_t)(row0 + 8) * N + col) =
                    make_float2(acc[m][n][2], acc[m][n][3]);
            }
        }
    }
}

// ---------------------------------------------------------------------------
// RoPE, in-place on fp16 qkv (q+k slots only; V untouched).
// Interleaved pairing, fp32 math — matches reference apply_rope.
// Safe in-place across graph replays: GEMM1 regenerates g_qkvh every call.
// ---------------------------------------------------------------------------
__global__ __launch_bounds__(256) void rope_f16_kernel(
    __half* __restrict__ qkv, const float* __restrict__ fc)
{
    int idx = blockIdx.x * blockDim.x + threadIdx.x;   // one thread per pair
    int d    = idx & 31;
    int slot = (idx >> 5) % 40;        // 0..31 q heads, 32..39 k heads
    int s    = idx / (40 * 32);
    if (s >= S_LEN) return;

    float c  = fc[s * 64 + d * 2 + 0];
    float sn = fc[s * 64 + d * 2 + 1];
    __half2* p = reinterpret_cast<__half2*>(qkv + (size_t)s * QKV_COLS + slot * 64 + 2 * d);
    float2 v = __half22float2(*p);
    *p = __floats2half2_rn(v.x * c - v.y * sn, v.y * c + v.x * sn);
}

// ---------------------------------------------------------------------------
// HMMA flash attention, causal, GQA. Q-tile 128 rows, KV-tile 64.
// 8 warps; warp owns 16 full rows (FA-2, warp-local softmax).
// smem: Q[128][144B] + 2 stages x (K+V)[64][144B] = 55296 B.
// ---------------------------------------------------------------------------
#define FK_ROW  144
#define FK_TILE (64 * FK_ROW)                  // 9216 B
#define FQ_SZ   (128 * FK_ROW)                 // 18432 B
#define FK_SMEM (FQ_SZ + 2 * 2 * FK_TILE)      // 55296 B

__global__ __launch_bounds__(256) void flash_hmma_kernel(
    const __half* __restrict__ qkvh, __half* __restrict__ Y)
{
    extern __shared__ char sm[];
    const uint32_t sb = smem_to_u32(sm);

    const int h  = blockIdx.y;
    const int kh = h >> 2;
    const int qt = blockIdx.x;          // 128-row q tile, 0..15
    const int q0 = qt * 128;
    const int njt = 2 * qt + 2;         // 64-col kv tiles to process

    const int tid  = threadIdx.x;
    const int w    = tid >> 5;          // 0..7
    const int lane = tid & 31;

    const float C2 = 0.18033688011112042f;   // (1/8) * log2(e)

    const uint32_t qAddr = (uint32_t)(w * 16 + (lane & 15)) * FK_ROW + (lane >> 4) * 16;
    const uint32_t kAddr = (uint32_t)(((lane >> 4) & 1) * 8 + (lane & 7)) * FK_ROW
                           + ((lane >> 3) & 1) * 16;
    const uint32_t vAddr = (uint32_t)((lane & 7) + ((lane >> 3) & 1) * 8) * FK_ROW
                           + (lane >> 4) * 16;

    // Q: 128 rows x 8 chunks = 1024 cp.asyncs, 4/thread
    auto load_q = [&]() {
#pragma unroll
        for (int i = 0; i < 4; i++) {
            int p = tid + i * 256, row = p >> 3, ch = p & 7;
            cp_async16(sb + (uint32_t)row * FK_ROW + ch * 16,
                       qkvh + (size_t)(q0 + row) * QKV_COLS + h * HD + ch * 8);
        }
    };
    // K+V: 64 rows x 8 chunks x 2 = 1024 cp.asyncs, 4/thread
    auto load_kv = [&](int s, int jt) {
        const int j0 = jt * 64;
        const uint32_t Kb = sb + FQ_SZ + s * 2 * FK_TILE;
#pragma unroll
        for (int i = 0; i < 2; i++) {
            int p = tid + i * 256, row = p >> 3, ch = p & 7;
            const __half* base = qkvh + (size_t)(j0 + row) * QKV_COLS + kh * HD + ch * 8;
            cp_async16(Kb + (uint32_t)row * FK_ROW + ch * 16, base + NH * HD);
            cp_async16(Kb + FK_TILE + (uint32_t)row * FK_ROW + ch * 16, base + (NH + NKV) * HD);
        }
    };

    load_q(); load_kv(0, 0); cp_commit();
    load_kv(1, 1); cp_commit();          // njt >= 2 always

    uint32_t aQ[4][4];
    float o[8][4];
#pragma unroll
    for (int n = 0; n < 8; n++)
#pragma unroll
        for (int q = 0; q < 4; q++) o[n][q] = 0.f;
    float m2[2] = { -1e30f, -1e30f };
    float l[2]  = { 0.f, 0.f };

    for (int jt = 0; jt < njt; jt++) {
        cp_wait1();
        __syncthreads();
        if (jt == 0) {
#pragma unroll
            for (int kc = 0; kc < 4; kc++) ldsm4(aQ[kc], sb + qAddr + kc * 32);
        }

        const uint32_t Kb = sb + FQ_SZ + (jt & 1) * 2 * FK_TILE;
        const uint32_t Vb = Kb + FK_TILE;

        float sc[8][4];
#pragma unroll
        for (int n = 0; n < 8; n++)
#pragma unroll
            for (int q = 0; q < 4; q++) sc[n][q] = 0.f;
#pragma unroll
        for (int p = 0; p < 4; p++) {
#pragma unroll
            for (int kc = 0; kc < 4; kc++) {
                uint32_t b[4];
                ldsm4(b, Kb + kAddr + (uint32_t)p * 16 * FK_ROW + kc * 32);
                mma16816f16(sc[2 * p + 0], aQ[kc], b + 0);
                mma16816f16(sc[2 * p + 1], aQ[kc], b + 2);
            }
        }

        // causal mask (global row/col compare; only last two kv tiles touch diag)
        if (jt >= 2 * qt) {
            const int j0 = jt * 64;
            const int rg = q0 + w * 16 + (lane >> 2);
            const int cb = j0 + (lane & 3) * 2;
#pragma unroll
            for (int n = 0; n < 8; n++) {
#pragma unroll
                for (int e = 0; e < 2; e++) {
                    int cg = cb + n * 8 + e;
                    if (cg > rg)     sc[n][e]     = -1e30f;
                    if (cg > rg + 8) sc[n][e + 2] = -1e30f;
                }
            }
        }

        // online softmax (log2 domain), warp-local rows
        uint32_t ph[8][2];
#pragma unroll
        for (int i = 0; i < 2; i++) {
            float mr = -1e30f;
#pragma unroll
            for (int n = 0; n < 8; n++)
                mr = fmaxf(mr, fmaxf(sc[n][2 * i], sc[n][2 * i + 1]));
            mr = fmaxf(mr, __shfl_xor_sync(0xffffffffu, mr, 1));
            mr = fmaxf(mr, __shfl_xor_sync(0xffffffffu, mr, 2));
            float m2n = fmaxf(m2[i], mr * C2);
            float r = fexp2(m2[i] - m2n);
            m2[i] = m2n;
            float sum = 0.f;
#pragma unroll
            for (int n = 0; n < 8; n++) {
                float p0 = fexp2(fmaf(sc[n][2 * i],     C2, -m2n));
                float p1 = fexp2(fmaf(sc[n][2 * i + 1], C2, -m2n));
                sum += p0 + p1;
                ph[n][i] = pack_h2(p0, p1);
            }
            sum += __shfl_xor_sync(0xffffffffu, sum, 1);
            sum += __shfl_xor_sync(0xffffffffu, sum, 2);
            l[i] = l[i] * r + sum;
#pragma unroll
            for (int n = 0; n < 8; n++) {
                o[n][2 * i]     *= r;
                o[n][2 * i + 1] *= r;
            }
        }

        // O += P @ V
#pragma unroll
        for (int kc = 0; kc < 4; kc++) {
            uint32_t a[4] = { ph[2 * kc][0], ph[2 * kc][1],
                              ph[2 * kc + 1][0], ph[2 * kc + 1][1] };
#pragma unroll
            for (int vp = 0; vp < 4; vp++) {
                uint32_t b[4];
                ldsm4t(b, Vb + vAddr + (uint32_t)kc * 16 * FK_ROW + vp * 32);
                mma16816f16(o[2 * vp + 0], a, b + 0);
                mma16816f16(o[2 * vp + 1], a, b + 2);
            }
        }

        __syncthreads();
        if (jt + 2 < njt) load_kv(jt & 1, jt + 2);
        cp_commit();
    }

    // epilogue: fp16 y
#pragma unroll
    for (int i = 0; i < 2; i++) {
        float inv = 1.f / l[i];
        int row = q0 + w * 16 + (lane >> 2) + 8 * i;
        __half* yr = Y + (size_t)row * H_DIM + h * HD + (lane & 3) * 2;
#pragma unroll
        for (int n = 0; n < 8; n++) {
            __half2 v = __floats2half2_rn(o[n][2 * i] * inv, o[n][2 * i + 1] * inv);
            *reinterpret_cast<__half2*>(yr + n * 8) = v;
        }
    }
}

// ---------------------------------------------------------------------------
// kernel_launch
// ---------------------------------------------------------------------------
extern "C" void kernel_launch(void* const* d_in, const int* in_sizes, int n_in,
                              void* d_out, int out_size)
{
    const float* x    = (const float*)d_in[0];
    const float* fc   = (const float*)d_in[1];
    const float* Wqkv = (const float*)d_in[3];
    const float* Wo   = (const float*)d_in[4];
    float* out = (float*)d_out;

    __half *qkvh, *ga, *gb;
    cudaGetSymbolAddress((void**)&qkvh, g_qkvh);
    cudaGetSymbolAddress((void**)&ga, g_a);
    cudaGetSymbolAddress((void**)&gb, g_b);

    cudaFuncSetAttribute(hgemm_kernel<true>,
                         cudaFuncAttributeMaxDynamicSharedMemorySize, HM_SMEM);
    cudaFuncSetAttribute(hgemm_kernel<false>,
                         cudaFuncAttributeMaxDynamicSharedMemorySize, HM_SMEM);
    cudaFuncSetAttribute(flash_hmma_kernel,
                         cudaFuncAttributeMaxDynamicSharedMemorySize, FK_SMEM);

    // 1) convert x and Wqkv to fp16
    {
        int n4 = S_LEN * H_DIM / 4;
        cvt_f16_kernel<<<n4 / 256, 256>>>((const float4*)x, (uint2*)ga, n4);
        int m4 = QKV_COLS * H_DIM / 4;
        cvt_f16_kernel<<<m4 / 256, 256>>>((const float4*)Wqkv, (uint2*)gb, m4);
    }

    // 2) QKV projection, fp16 output: g_qkvh = x @ Wqkv^T
    {
        dim3 grid(QKV_COLS / 128, S_LEN / 128);
        hgemm_kernel<true><<<grid, 256, HM_SMEM>>>(ga, gb, qkvh, S_LEN, QKV_COLS, H_DIM);
    }

    // 3) RoPE in-place on fp16 q/k
    {
        int total = S_LEN * 40 * 32;
        rope_f16_kernel<<<total / 256, 256>>>(qkvh, fc);
    }

    // 4) convert Wo to fp16 (g_b free after gemm1)
    {
        int n4 = S_LEN * H_DIM / 4;
        cvt_f16_kernel<<<n4 / 256, 256>>>((const float4*)Wo, (uint2*)gb, n4);
    }

    // 5) HMMA flash attention (q-tile 128) -> g_a (fp16 y; x no longer needed)
    {
        dim3 grid(S_LEN / 128, NH);
        flash_hmma_kernel<<<grid, 256, FK_SMEM>>>(qkvh, ga);
    }

    // 6) output projection, fp32 output: out = y @ Wo^T
    {
        dim3 grid(H_DIM / 128, S_LEN / 128);
        hgemm_kernel<false><<<grid, 256, HM_SMEM>>>(ga, gb, out, S_LEN, H_DIM, H_DIM);
    }
}

// round 7
// speedup vs baseline: 7.0672x; 1.1135x over previous
#include <cuda_runtime.h>
#include <cuda_fp16.h>
#include <cstdint>

// Problem constants (fixed by the dataset)
#define S_LEN 2048
#define H_DIM 2048
#define NH    32
#define NKV   8
#define HD    64
#define QKV_COLS ((NH + 2*NKV) * HD)   // 3072

// ---------------------------------------------------------------------------
// Scratch (allocation-free rule: __device__ globals)
// ---------------------------------------------------------------------------
__device__ __align__(16) __half g_qkvh[(size_t)S_LEN * QKV_COLS]; // 12 MB
__device__ __align__(16) __half g_a[(size_t)S_LEN * H_DIM];       // 8 MB (x, then y)
__device__ __align__(16) __half g_b[(size_t)QKV_COLS * H_DIM];    // 12 MB (Wqkv)
__device__ __align__(16) __half g_c[(size_t)H_DIM * H_DIM];       // 8 MB (Wo)

// ---------------------------------------------------------------------------
// Arch-agnostic PTX helpers (sm_80+ ISA; tcgen05 rejected by plain-sm_103 ptxas)
// ---------------------------------------------------------------------------
__device__ __forceinline__ uint32_t smem_to_u32(const void* p) {
    uint32_t a;
    asm("{ .reg .u64 t; cvta.to.shared.u64 t, %1; cvt.u32.u64 %0, t; }"
        : "=r"(a) : "l"(p));
    return a;
}
__device__ __forceinline__ void cp_async16(uint32_t smem, const void* gptr) {
    asm volatile("cp.async.cg.shared.global [%0], [%1], 16;"
                 :: "r"(smem), "l"(__cvta_generic_to_global(gptr)) : "memory");
}
__device__ __forceinline__ void cp_commit() {
    asm volatile("cp.async.commit_group;" ::: "memory");
}
__device__ __forceinline__ void cp_wait1() {
    asm volatile("cp.async.wait_group 1;" ::: "memory");
}
__device__ __forceinline__ void cp_wait2() {
    asm volatile("cp.async.wait_group 2;" ::: "memory");
}
__device__ __forceinline__ void ldsm4(uint32_t* r, uint32_t addr) {
    asm volatile("ldmatrix.sync.aligned.m8n8.x4.shared.b16 {%0,%1,%2,%3}, [%4];"
                 : "=r"(r[0]), "=r"(r[1]), "=r"(r[2]), "=r"(r[3]) : "r"(addr));
}
__device__ __forceinline__ void ldsm4t(uint32_t* r, uint32_t addr) {
    asm volatile("ldmatrix.sync.aligned.m8n8.x4.trans.shared.b16 {%0,%1,%2,%3}, [%4];"
                 : "=r"(r[0]), "=r"(r[1]), "=r"(r[2]), "=r"(r[3]) : "r"(addr));
}
__device__ __forceinline__ void mma16816f16(float* c, const uint32_t* a, const uint32_t* b) {
    asm volatile(
        "mma.sync.aligned.m16n8k16.row.col.f32.f16.f16.f32 "
        "{%0,%1,%2,%3}, {%4,%5,%6,%7}, {%8,%9}, {%0,%1,%2,%3};"
        : "+f"(c[0]), "+f"(c[1]), "+f"(c[2]), "+f"(c[3])
        : "r"(a[0]), "r"(a[1]), "r"(a[2]), "r"(a[3]), "r"(b[0]), "r"(b[1]));
}
__device__ __forceinline__ uint32_t pack_h2(float a, float b) {
    __half2 h = __floats2half2_rn(a, b);
    return *reinterpret_cast<uint32_t*>(&h);
}

// Fast 2^d on the FMA pipe (d <= 0; clamped). ~1e-6 rel accuracy.
__device__ __forceinline__ float fexp2(float d) {
    d = fmaxf(d, -80.0f);
    float t  = d + 12582912.0f;
    float nf = t - 12582912.0f;
    float f  = d - nf;
    int   n  = __float_as_int(t) - 0x4B400000;
    float p  = 1.3333558146e-3f;
    p = fmaf(p, f, 9.6181291e-3f);
    p = fmaf(p, f, 5.5504108664e-2f);
    p = fmaf(p, f, 2.4022650696e-1f);
    p = fmaf(p, f, 6.9314718056e-1f);
    p = fmaf(p, f, 1.0f);
    return __int_as_float(__float_as_int(p) + (n << 23));
}

// ---------------------------------------------------------------------------
// Fused fp32 -> fp16 convert for x, Wqkv, Wo in one launch
// ---------------------------------------------------------------------------
#define N4_X  (S_LEN * H_DIM / 4)        // 1048576
#define N4_WQ (QKV_COLS * H_DIM / 4)     // 1572864
#define N4_WO (H_DIM * H_DIM / 4)        // 1048576
#define N4_ALL (N4_X + N4_WQ + N4_WO)

__global__ __launch_bounds__(256) void cvt_all_kernel(
    const float4* __restrict__ x, const float4* __restrict__ wq,
    const float4* __restrict__ wo,
    uint2* __restrict__ ox, uint2* __restrict__ owq, uint2* __restrict__ owo)
{
    int i = blockIdx.x * blockDim.x + threadIdx.x;
    const float4* in;
    uint2* out;
    int j;
    if (i < N4_X)                { in = x;  out = ox;  j = i; }
    else if (i < N4_X + N4_WQ)   { in = wq; out = owq; j = i - N4_X; }
    else if (i < N4_ALL)         { in = wo; out = owo; j = i - N4_X - N4_WQ; }
    else return;
    float4 f = in[j];
    out[j] = make_uint2(pack_h2(f.x, f.y), pack_h2(f.z, f.w));
}

// ---------------------------------------------------------------------------
// HMMA TN GEMM, fp16 in, templated output (fp32 or fp16) and optional fused
// RoPE epilogue (GEMM1: qkv projection). RoPE uses the fact that the mma
// fragment gives each thread adjacent col pairs (col even) == RoPE pairs.
// ---------------------------------------------------------------------------
#define HM_ROWB   80
#define HM_TILE_B (128 * HM_ROWB)
#define HM_STAGE  (2 * HM_TILE_B)
#define HM_SMEM   (4 * HM_STAGE)

template <bool HALF_OUT, bool ROPE>
__global__ __launch_bounds__(256, 2) void hgemm_kernel(
    const __half* __restrict__ A, const __half* __restrict__ B,
    void* __restrict__ Cv, const float* __restrict__ fc, int M, int N, int K)
{
    extern __shared__ char smem[];
    const uint32_t sbase = smem_to_u32(smem);

    const int tid  = threadIdx.x;
    const int wid  = tid >> 5;
    const int lane = tid & 31;
    const int warpM = wid >> 1;
    const int warpN = wid & 1;
    const int bm = blockIdx.y * 128;
    const int bn = blockIdx.x * 128;

    const int ldrow = tid >> 2;
    const int ldc   = (tid & 3) * 16;
    const __half* gA0 = A + (size_t)(bm + ldrow) * K + (ldc >> 1);
    const __half* gB0 = B + (size_t)(bn + ldrow) * K + (ldc >> 1);

    const uint32_t aAddrBase =
        (uint32_t)(warpM * 32 + (lane & 15)) * HM_ROWB + (lane >> 4) * 16;
    const uint32_t bAddrBase =
        (uint32_t)(warpN * 64 + ((lane >> 4) & 1) * 8 + (lane & 7)) * HM_ROWB
        + ((lane >> 3) & 1) * 16;

    float acc[2][8][4];
#pragma unroll
    for (int m = 0; m < 2; m++)
#pragma unroll
        for (int n = 0; n < 8; n++)
#pragma unroll
            for (int q = 0; q < 4; q++) acc[m][n][q] = 0.f;

    const int nchunk = K / 32;

    auto load_stage = [&](int s, int c) {
        const uint32_t st = sbase + s * HM_STAGE;
        const int k0 = c * 32;
        cp_async16(st + (uint32_t)ldrow * HM_ROWB + ldc, gA0 + k0);
        cp_async16(st + (uint32_t)(ldrow + 64) * HM_ROWB + ldc, gA0 + (size_t)64 * K + k0);
        cp_async16(st + HM_TILE_B + (uint32_t)ldrow * HM_ROWB + ldc, gB0 + k0);
        cp_async16(st + HM_TILE_B + (uint32_t)(ldrow + 64) * HM_ROWB + ldc, gB0 + (size_t)64 * K + k0);
    };

    load_stage(0, 0); cp_commit();
    load_stage(1, 1); cp_commit();
    load_stage(2, 2); cp_commit();

    for (int c = 0; c < nchunk; c++) {
        cp_wait2();
        __syncthreads();
        if (c + 3 < nchunk) load_stage((c + 3) & 3, c + 3);
        cp_commit();

        const uint32_t st = sbase + (c & 3) * HM_STAGE;
        const uint32_t sA = st + aAddrBase;
        const uint32_t sB = st + HM_TILE_B + bAddrBase;

#pragma unroll
        for (int ks = 0; ks < 2; ks++) {
            const uint32_t ko = ks * 32;
            uint32_t a[2][4];
            ldsm4(a[0], sA + ko);
            ldsm4(a[1], sA + 16 * HM_ROWB + ko);
#pragma unroll
            for (int p = 0; p < 4; p++) {
                uint32_t b[4];
                ldsm4(b, sB + (uint32_t)p * 16 * HM_ROWB + ko);
#pragma unroll
                for (int m = 0; m < 2; m++) {
                    mma16816f16(acc[m][2 * p + 0], a[m], b + 0);
                    mma16816f16(acc[m][2 * p + 1], a[m], b + 2);
                }
            }
        }
    }

    // --- fused RoPE (uniform per CTA: q/k head cols are [0,2560), 128-aligned)
    if (ROPE && bn < NH * HD + NKV * HD) {
        const int d0 = lane & 3;                      // d = n*4 + d0
#pragma unroll
        for (int m = 0; m < 2; m++) {
            const int r0 = bm + warpM * 32 + m * 16 + (lane >> 2);
#pragma unroll
            for (int n = 0; n < 8; n++) {
                const int d = n * 4 + d0;
                float2 cs0 = *reinterpret_cast<const float2*>(fc + (size_t)r0 * 64 + d * 2);
                float2 cs1 = *reinterpret_cast<const float2*>(fc + (size_t)(r0 + 8) * 64 + d * 2);
                float x0 = acc[m][n][0], x1 = acc[m][n][1];
                acc[m][n][0] = x0 * cs0.x - x1 * cs0.y;
                acc[m][n][1] = x1 * cs0.x + x0 * cs0.y;
                float y0 = acc[m][n][2], y1 = acc[m][n][3];
                acc[m][n][2] = y0 * cs1.x - y1 * cs1.y;
                acc[m][n][3] = y1 * cs1.x + y0 * cs1.y;
            }
        }
    }

    const int qrow = lane >> 2;
    const int qcol = (lane & 3) * 2;
#pragma unroll
    for (int m = 0; m < 2; m++) {
        const int row0 = bm + warpM * 32 + m * 16 + qrow;
#pragma unroll
        for (int n = 0; n < 8; n++) {
            const int col = bn + warpN * 64 + n * 8 + qcol;
            if (HALF_OUT) {
                __half* C = (__half*)Cv;
                *reinterpret_cast<uint32_t*>(C + (size_t)row0 * N + col) =
                    pack_h2(acc[m][n][0], acc[m][n][1]);
                *reinterpret_cast<uint32_t*>(C + (size_t)(row0 + 8) * N + col) =
                    pack_h2(acc[m][n][2], acc[m][n][3]);
            } else {
                float* C = (float*)Cv;
                *reinterpret_cast<float2*>(C + (size_t)row0 * N + col) =
                    make_float2(acc[m][n][0], acc[m][n][1]);
                *reinterpret_cast<float2*>(C + (size_t)(row0 + 8) * N + col) =
                    make_float2(acc[m][n][2], acc[m][n][3]);
            }
        }
    }
}

// ---------------------------------------------------------------------------
// HMMA flash attention, causal, GQA. Q-tile 128 rows, KV-tile 64.
// 8 warps; warp owns 16 full rows (FA-2, warp-local softmax).
// 1D grid, LPT order: highest-qt (most work) CTAs launch first.
// ---------------------------------------------------------------------------
#define FK_ROW  144
#define FK_TILE (64 * FK_ROW)                  // 9216 B
#define FQ_SZ   (128 * FK_ROW)                 // 18432 B
#define FK_SMEM (FQ_SZ + 2 * 2 * FK_TILE)      // 55296 B
#define N_QT    (S_LEN / 128)                  // 16

__global__ __launch_bounds__(256) void flash_hmma_kernel(
    const __half* __restrict__ qkvh, __half* __restrict__ Y)
{
    extern __shared__ char sm[];
    const uint32_t sb = smem_to_u32(sm);

    const int bx = blockIdx.x;
    const int qt = (N_QT - 1) - (bx >> 5);     // longest-first
    const int h  = bx & 31;
    const int kh = h >> 2;
    const int q0 = qt * 128;
    const int njt = 2 * qt + 2;

    const int tid  = threadIdx.x;
    const int w    = tid >> 5;
    const int lane = tid & 31;

    const float C2 = 0.18033688011112042f;   // (1/8) * log2(e)

    const uint32_t qAddr = (uint32_t)(w * 16 + (lane & 15)) * FK_ROW + (lane >> 4) * 16;
    const uint32_t kAddr = (uint32_t)(((lane >> 4) & 1) * 8 + (lane & 7)) * FK_ROW
                           + ((lane >> 3) & 1) * 16;
    const uint32_t vAddr = (uint32_t)((lane & 7) + ((lane >> 3) & 1) * 8) * FK_ROW
                           + (lane >> 4) * 16;

    auto load_q = [&]() {
#pragma unroll
        for (int i = 0; i < 4; i++) {
            int p = tid + i * 256, row = p >> 3, ch = p & 7;
            cp_async16(sb + (uint32_t)row * FK_ROW + ch * 16,
                       qkvh + (size_t)(q0 + row) * QKV_COLS + h * HD + ch * 8);
        }
    };
    auto load_kv = [&](int s, int jt) {
        const int j0 = jt * 64;
        const uint32_t Kb = sb + FQ_SZ + s * 2 * FK_TILE;
#pragma unroll
        for (int i = 0; i < 2; i++) {
            int p = tid + i * 256, row = p >> 3, ch = p & 7;
            const __half* base = qkvh + (size_t)(j0 + row) * QKV_COLS + kh * HD + ch * 8;
            cp_async16(Kb + (uint32_t)row * FK_ROW + ch * 16, base + NH * HD);
            cp_async16(Kb + FK_TILE + (uint32_t)row * FK_ROW + ch * 16, base + (NH + NKV) * HD);
        }
    };

    load_q(); load_kv(0, 0); cp_commit();
    load_kv(1, 1); cp_commit();          // njt >= 2 always

    uint32_t aQ[4][4];
    float o[8][4];
#pragma unroll
    for (int n = 0; n < 8; n++)
#pragma unroll
        for (int q = 0; q < 4; q++) o[n][q] = 0.f;
    float m2[2] = { -1e30f, -1e30f };
    float l[2]  = { 0.f, 0.f };

    for (int jt = 0; jt < njt; jt++) {
        cp_wait1();
        __syncthreads();
        if (jt == 0) {
#pragma unroll
            for (int kc = 0; kc < 4; kc++) ldsm4(aQ[kc], sb + qAddr + kc * 32);
        }

        const uint32_t Kb = sb + FQ_SZ + (jt & 1) * 2 * FK_TILE;
        const uint32_t Vb = Kb + FK_TILE;

        float sc[8][4];
#pragma unroll
        for (int n = 0; n < 8; n++)
#pragma unroll
            for (int q = 0; q < 4; q++) sc[n][q] = 0.f;
#pragma unroll
        for (int p = 0; p < 4; p++) {
#pragma unroll
            for (int kc = 0; kc < 4; kc++) {
                uint32_t b[4];
                ldsm4(b, Kb + kAddr + (uint32_t)p * 16 * FK_ROW + kc * 32);
                mma16816f16(sc[2 * p + 0], aQ[kc], b + 0);
                mma16816f16(sc[2 * p + 1], aQ[kc], b + 2);
            }
        }

        // causal mask (only last two kv tiles touch the diagonal)
        if (jt >= 2 * qt) {
            const int j0 = jt * 64;
            const int rg = q0 + w * 16 + (lane >> 2);
            const int cb = j0 + (lane & 3) * 2;
#pragma unroll
            for (int n = 0; n < 8; n++) {
#pragma unroll
                for (int e = 0; e < 2; e++) {
                    int cg = cb + n * 8 + e;
                    if (cg > rg)     sc[n][e]     = -1e30f;
                    if (cg > rg + 8) sc[n][e + 2] = -1e30f;
                }
            }
        }

        // online softmax (log2 domain), warp-local rows
        uint32_t ph[8][2];
#pragma unroll
        for (int i = 0; i < 2; i++) {
            float mr = -1e30f;
#pragma unroll
            for (int n = 0; n < 8; n++)
                mr = fmaxf(mr, fmaxf(sc[n][2 * i], sc[n][2 * i + 1]));
            mr = fmaxf(mr, __shfl_xor_sync(0xffffffffu, mr, 1));
            mr = fmaxf(mr, __shfl_xor_sync(0xffffffffu, mr, 2));
            float m2n = fmaxf(m2[i], mr * C2);
            float r = fexp2(m2[i] - m2n);
            m2[i] = m2n;
            float sum = 0.f;
#pragma unroll
            for (int n = 0; n < 8; n++) {
                float p0 = fexp2(fmaf(sc[n][2 * i],     C2, -m2n));
                float p1 = fexp2(fmaf(sc[n][2 * i + 1], C2, -m2n));
                sum += p0 + p1;
                ph[n][i] = pack_h2(p0, p1);
            }
            sum += __shfl_xor_sync(0xffffffffu, sum, 1);
            sum += __shfl_xor_sync(0xffffffffu, sum, 2);
            l[i] = l[i] * r + sum;
#pragma unroll
            for (int n = 0; n < 8; n++) {
                o[n][2 * i]     *= r;
                o[n][2 * i + 1] *= r;
            }
        }

        // O += P @ V
#pragma unroll
        for (int kc = 0; kc < 4; kc++) {
            uint32_t a[4] = { ph[2 * kc][0], ph[2 * kc][1],
                              ph[2 * kc + 1][0], ph[2 * kc + 1][1] };
#pragma unroll
            for (int vp = 0; vp < 4; vp++) {
                uint32_t b[4];
                ldsm4t(b, Vb + vAddr + (uint32_t)kc * 16 * FK_ROW + vp * 32);
                mma16816f16(o[2 * vp + 0], a, b + 0);
                mma16816f16(o[2 * vp + 1], a, b + 2);
            }
        }

        __syncthreads();
        if (jt + 2 < njt) load_kv(jt & 1, jt + 2);
        cp_commit();
    }

    // epilogue: fp16 y
#pragma unroll
    for (int i = 0; i < 2; i++) {
        float inv = 1.f / l[i];
        int row = q0 + w * 16 + (lane >> 2) + 8 * i;
        __half* yr = Y + (size_t)row * H_DIM + h * HD + (lane & 3) * 2;
#pragma unroll
        for (int n = 0; n < 8; n++) {
            __half2 v = __floats2half2_rn(o[n][2 * i] * inv, o[n][2 * i + 1] * inv);
            *reinterpret_cast<__half2*>(yr + n * 8) = v;
        }
    }
}

// ---------------------------------------------------------------------------
// kernel_launch: 4 launches total
// ---------------------------------------------------------------------------
extern "C" void kernel_launch(void* const* d_in, const int* in_sizes, int n_in,
                              void* d_out, int out_size)
{
    const float* x    = (const float*)d_in[0];
    const float* fc   = (const float*)d_in[1];
    const float* Wqkv = (const float*)d_in[3];
    const float* Wo   = (const float*)d_in[4];
    float* out = (float*)d_out;

    __half *qkvh, *ga, *gb, *gc;
    cudaGetSymbolAddress((void**)&qkvh, g_qkvh);
    cudaGetSymbolAddress((void**)&ga, g_a);
    cudaGetSymbolAddress((void**)&gb, g_b);
    cudaGetSymbolAddress((void**)&gc, g_c);

    cudaFuncSetAttribute((const void*)hgemm_kernel<true, true>,
                         cudaFuncAttributeMaxDynamicSharedMemorySize, HM_SMEM);
    cudaFuncSetAttribute((const void*)hgemm_kernel<false, false>,
                         cudaFuncAttributeMaxDynamicSharedMemorySize, HM_SMEM);
    cudaFuncSetAttribute((const void*)flash_hmma_kernel,
                         cudaFuncAttributeMaxDynamicSharedMemorySize, FK_SMEM);

    // 1) fused convert: x, Wqkv, Wo -> fp16
    cvt_all_kernel<<<(N4_ALL + 255) / 256, 256>>>(
        (const float4*)x, (const float4*)Wqkv, (const float4*)Wo,
        (uint2*)ga, (uint2*)gb, (uint2*)gc);

    // 2) QKV projection with fused RoPE, fp16 output
    {
        dim3 grid(QKV_COLS / 128, S_LEN / 128);
        hgemm_kernel<true, true><<<grid, 256, HM_SMEM>>>(
            ga, gb, qkvh, fc, S_LEN, QKV_COLS, H_DIM);
    }

    // 3) HMMA flash attention (q-tile 128, LPT order) -> g_a (fp16 y)
    flash_hmma_kernel<<<N_QT * NH, 256, FK_SMEM>>>(qkvh, ga);

    // 4) output projection, fp32 output: out = y @ Wo^T
    {
        dim3 grid(H_DIM / 128, S_LEN / 128);
        hgemm_kernel<false, false><<<grid, 256, HM_SMEM>>>(
            ga, gc, out, nullptr, S_LEN, H_DIM, H_DIM);
    }
}

// round 8
// speedup vs baseline: 7.2037x; 1.0193x over previous
#include <cuda_runtime.h>
#include <cuda_fp16.h>
#include <cstdint>

// Problem constants (fixed by the dataset)
#define S_LEN 2048
#define H_DIM 2048
#define NH    32
#define NKV   8
#define HD    64
#define QKV_COLS ((NH + 2*NKV) * HD)   // 3072

// ---------------------------------------------------------------------------
// Scratch (allocation-free rule: __device__ globals)
// ---------------------------------------------------------------------------
__device__ __align__(16) __half g_qkvh[(size_t)S_LEN * QKV_COLS]; // 12 MB
__device__ __align__(16) __half g_a[(size_t)S_LEN * H_DIM];       // 8 MB (x, then y)
__device__ __align__(16) __half g_b[(size_t)QKV_COLS * H_DIM];    // 12 MB (Wqkv)
__device__ __align__(16) __half g_c[(size_t)H_DIM * H_DIM];       // 8 MB (Wo)

// ---------------------------------------------------------------------------
// Arch-agnostic PTX helpers (sm_80+ ISA; tcgen05 rejected by plain-sm_103 ptxas)
// ---------------------------------------------------------------------------
__device__ __forceinline__ uint32_t smem_to_u32(const void* p) {
    uint32_t a;
    asm("{ .reg .u64 t; cvta.to.shared.u64 t, %1; cvt.u32.u64 %0, t; }"
        : "=r"(a) : "l"(p));
    return a;
}
__device__ __forceinline__ void cp_async16(uint32_t smem, const void* gptr) {
    asm volatile("cp.async.cg.shared.global [%0], [%1], 16;"
                 :: "r"(smem), "l"(__cvta_generic_to_global(gptr)) : "memory");
}
__device__ __forceinline__ void cp_commit() {
    asm volatile("cp.async.commit_group;" ::: "memory");
}
__device__ __forceinline__ void cp_wait1() {
    asm volatile("cp.async.wait_group 1;" ::: "memory");
}
__device__ __forceinline__ void cp_wait2() {
    asm volatile("cp.async.wait_group 2;" ::: "memory");
}
__device__ __forceinline__ void ldsm4(uint32_t* r, uint32_t addr) {
    asm volatile("ldmatrix.sync.aligned.m8n8.x4.shared.b16 {%0,%1,%2,%3}, [%4];"
                 : "=r"(r[0]), "=r"(r[1]), "=r"(r[2]), "=r"(r[3]) : "r"(addr));
}
__device__ __forceinline__ void ldsm4t(uint32_t* r, uint32_t addr) {
    asm volatile("ldmatrix.sync.aligned.m8n8.x4.trans.shared.b16 {%0,%1,%2,%3}, [%4];"
                 : "=r"(r[0]), "=r"(r[1]), "=r"(r[2]), "=r"(r[3]) : "r"(addr));
}
__device__ __forceinline__ void mma16816f16(float* c, const uint32_t* a, const uint32_t* b) {
    asm volatile(
        "mma.sync.aligned.m16n8k16.row.col.f32.f16.f16.f32 "
        "{%0,%1,%2,%3}, {%4,%5,%6,%7}, {%8,%9}, {%0,%1,%2,%3};"
        : "+f"(c[0]), "+f"(c[1]), "+f"(c[2]), "+f"(c[3])
        : "r"(a[0]), "r"(a[1]), "r"(a[2]), "r"(a[3]), "r"(b[0]), "r"(b[1]));
}
__device__ __forceinline__ uint32_t pack_h2(float a, float b) {
    __half2 h = __floats2half2_rn(a, b);
    return *reinterpret_cast<uint32_t*>(&h);
}

// ---- packed f32x2 ops (Blackwell base ISA, sm_100 family incl. sm_103) ----
typedef unsigned long long u64;
__device__ __forceinline__ u64 pk2(float a, float b) {
    u64 r; asm("mov.b64 %0, {%1, %2};" : "=l"(r) : "f"(a), "f"(b)); return r;
}
__device__ __forceinline__ void upk2(u64 v, float& a, float& b) {
    asm("mov.b64 {%0, %1}, %2;" : "=f"(a), "=f"(b) : "l"(v));
}
__device__ __forceinline__ u64 add2_(u64 a, u64 b) {
    u64 r; asm("add.rn.f32x2 %0, %1, %2;" : "=l"(r) : "l"(a), "l"(b)); return r;
}
__device__ __forceinline__ u64 fma2_(u64 a, u64 b, u64 c) {
    u64 r; asm("fma.rn.f32x2 %0, %1, %2, %3;" : "=l"(r) : "l"(a), "l"(b), "l"(c)); return r;
}
__device__ __forceinline__ u64 dup2(float x) {
    unsigned int b = __float_as_uint(x);
    return ((u64)b << 32) | b;
}

// Scalar fast 2^d (clamped; used only for the per-pass rescale factor).
__device__ __forceinline__ float fexp2(float d) {
    d = fmaxf(d, -80.0f);
    float t  = d + 12582912.0f;
    float nf = t - 12582912.0f;
    float f  = d - nf;
    int   n  = __float_as_int(t) - 0x4B400000;
    float p  = 9.6181291e-3f;
    p = fmaf(p, f, 5.5504108664e-2f);
    p = fmaf(p, f, 2.4022650696e-1f);
    p = fmaf(p, f, 6.9314718056e-1f);
    p = fmaf(p, f, 1.0f);
    return __int_as_float(__float_as_int(p) + (n << 23));
}

// Packed 2^(a0), 2^(a1). Args MUST be in [-126, 0] (guaranteed by the -500
// mask sentinel and score bounds) — no clamp, deg-4 poly (~4e-5 rel err).
#define FEXP2X2(arg, r0, r1) do {                                           \
    u64 _t  = add2_(arg, kMAG);                                             \
    u64 _nf = add2_(_t, kNMAG);                                             \
    u64 _f  = fma2_(_nf, kNEG1, arg);                                       \
    u64 _p  = fma2_(kC4, _f, kC3);                                          \
    _p = fma2_(_p, _f, kC2);                                                \
    _p = fma2_(_p, _f, kC1);                                                \
    _p = fma2_(_p, _f, kONE);                                               \
    float _t0, _t1, _p0, _p1;                                               \
    upk2(_t, _t0, _t1);                                                     \
    upk2(_p, _p0, _p1);                                                     \
    int _n0 = (__float_as_int(_t0) - 0x4B400000) << 23;                     \
    int _n1 = (__float_as_int(_t1) - 0x4B400000) << 23;                     \
    r0 = __int_as_float(__float_as_int(_p0) + _n0);                         \
    r1 = __int_as_float(__float_as_int(_p1) + _n1);                         \
} while (0)

// ---------------------------------------------------------------------------
// Fused fp32 -> fp16 convert for x, Wqkv, Wo in one launch
// ---------------------------------------------------------------------------
#define N4_X  (S_LEN * H_DIM / 4)
#define N4_WQ (QKV_COLS * H_DIM / 4)
#define N4_WO (H_DIM * H_DIM / 4)
#define N4_ALL (N4_X + N4_WQ + N4_WO)

__global__ __launch_bounds__(256) void cvt_all_kernel(
    const float4* __restrict__ x, const float4* __restrict__ wq,
    const float4* __restrict__ wo,
    uint2* __restrict__ ox, uint2* __restrict__ owq, uint2* __restrict__ owo)
{
    int i = blockIdx.x * blockDim.x + threadIdx.x;
    const float4* in;
    uint2* out;
    int j;
    if (i < N4_X)                { in = x;  out = ox;  j = i; }
    else if (i < N4_X + N4_WQ)   { in = wq; out = owq; j = i - N4_X; }
    else if (i < N4_ALL)         { in = wo; out = owo; j = i - N4_X - N4_WQ; }
    else return;
    float4 f = in[j];
    out[j] = make_uint2(pack_h2(f.x, f.y), pack_h2(f.z, f.w));
}

// ---------------------------------------------------------------------------
// HMMA TN GEMM, fp16 in, templated output (fp32 or fp16) and optional fused
// RoPE epilogue (GEMM1). Mainloop validated R4-R7.
// ---------------------------------------------------------------------------
#define HM_ROWB   80
#define HM_TILE_B (128 * HM_ROWB)
#define HM_STAGE  (2 * HM_TILE_B)
#define HM_SMEM   (4 * HM_STAGE)

template <bool HALF_OUT, bool ROPE>
__global__ __launch_bounds__(256, 2) void hgemm_kernel(
    const __half* __restrict__ A, const __half* __restrict__ B,
    void* __restrict__ Cv, const float* __restrict__ fc, int M, int N, int K)
{
    extern __shared__ char smem[];
    const uint32_t sbase = smem_to_u32(smem);

    const int tid  = threadIdx.x;
    const int wid  = tid >> 5;
    const int lane = tid & 31;
    const int warpM = wid >> 1;
    const int warpN = wid & 1;
    const int bm = blockIdx.y * 128;
    const int bn = blockIdx.x * 128;

    const int ldrow = tid >> 2;
    const int ldc   = (tid & 3) * 16;
    const __half* gA0 = A + (size_t)(bm + ldrow) * K + (ldc >> 1);
    const __half* gB0 = B + (size_t)(bn + ldrow) * K + (ldc >> 1);

    const uint32_t aAddrBase =
        (uint32_t)(warpM * 32 + (lane & 15)) * HM_ROWB + (lane >> 4) * 16;
    const uint32_t bAddrBase =
        (uint32_t)(warpN * 64 + ((lane >> 4) & 1) * 8 + (lane & 7)) * HM_ROWB
        + ((lane >> 3) & 1) * 16;

    float acc[2][8][4];
#pragma unroll
    for (int m = 0; m < 2; m++)
#pragma unroll
        for (int n = 0; n < 8; n++)
#pragma unroll
            for (int q = 0; q < 4; q++) acc[m][n][q] = 0.f;

    const int nchunk = K / 32;

    auto load_stage = [&](int s, int c) {
        const uint32_t st = sbase + s * HM_STAGE;
        const int k0 = c * 32;
        cp_async16(st + (uint32_t)ldrow * HM_ROWB + ldc, gA0 + k0);
        cp_async16(st + (uint32_t)(ldrow + 64) * HM_ROWB + ldc, gA0 + (size_t)64 * K + k0);
        cp_async16(st + HM_TILE_B + (uint32_t)ldrow * HM_ROWB + ldc, gB0 + k0);
        cp_async16(st + HM_TILE_B + (uint32_t)(ldrow + 64) * HM_ROWB + ldc, gB0 + (size_t)64 * K + k0);
    };

    load_stage(0, 0); cp_commit();
    load_stage(1, 1); cp_commit();
    load_stage(2, 2); cp_commit();

    for (int c = 0; c < nchunk; c++) {
        cp_wait2();
        __syncthreads();
        if (c + 3 < nchunk) load_stage((c + 3) & 3, c + 3);
        cp_commit();

        const uint32_t st = sbase + (c & 3) * HM_STAGE;
        const uint32_t sA = st + aAddrBase;
        const uint32_t sB = st + HM_TILE_B + bAddrBase;

#pragma unroll
        for (int ks = 0; ks < 2; ks++) {
            const uint32_t ko = ks * 32;
            uint32_t a[2][4];
            ldsm4(a[0], sA + ko);
            ldsm4(a[1], sA + 16 * HM_ROWB + ko);
#pragma unroll
            for (int p = 0; p < 4; p++) {
                uint32_t b[4];
                ldsm4(b, sB + (uint32_t)p * 16 * HM_ROWB + ko);
#pragma unroll
                for (int m = 0; m < 2; m++) {
                    mma16816f16(acc[m][2 * p + 0], a[m], b + 0);
                    mma16816f16(acc[m][2 * p + 1], a[m], b + 2);
                }
            }
        }
    }

    // fused RoPE (uniform per CTA: q/k head cols are [0,2560), 128-aligned)
    if (ROPE && bn < NH * HD + NKV * HD) {
        const int d0 = lane & 3;
#pragma unroll
        for (int m = 0; m < 2; m++) {
            const int r0 = bm + warpM * 32 + m * 16 + (lane >> 2);
#pragma unroll
            for (int n = 0; n < 8; n++) {
                const int d = n * 4 + d0;
                float2 cs0 = *reinterpret_cast<const float2*>(fc + (size_t)r0 * 64 + d * 2);
                float2 cs1 = *reinterpret_cast<const float2*>(fc + (size_t)(r0 + 8) * 64 + d * 2);
                float x0 = acc[m][n][0], x1 = acc[m][n][1];
                acc[m][n][0] = x0 * cs0.x - x1 * cs0.y;
                acc[m][n][1] = x1 * cs0.x + x0 * cs0.y;
                float y0 = acc[m][n][2], y1 = acc[m][n][3];
                acc[m][n][2] = y0 * cs1.x - y1 * cs1.y;
                acc[m][n][3] = y1 * cs1.x + y0 * cs1.y;
            }
        }
    }

    const int qrow = lane >> 2;
    const int qcol = (lane & 3) * 2;
#pragma unroll
    for (int m = 0; m < 2; m++) {
        const int row0 = bm + warpM * 32 + m * 16 + qrow;
#pragma unroll
        for (int n = 0; n < 8; n++) {
            const int col = bn + warpN * 64 + n * 8 + qcol;
            if (HALF_OUT) {
                __half* C = (__half*)Cv;
                *reinterpret_cast<uint32_t*>(C + (size_t)row0 * N + col) =
                    pack_h2(acc[m][n][0], acc[m][n][1]);
                *reinterpret_cast<uint32_t*>(C + (size_t)(row0 + 8) * N + col) =
                    pack_h2(acc[m][n][2], acc[m][n][3]);
            } else {
                float* C = (float*)Cv;
                *reinterpret_cast<float2*>(C + (size_t)row0 * N + col) =
                    make_float2(acc[m][n][0], acc[m][n][1]);
                *reinterpret_cast<float2*>(C + (size_t)(row0 + 8) * N + col) =
                    make_float2(acc[m][n][2], acc[m][n][3]);
            }
        }
    }
}

// ---------------------------------------------------------------------------
// HMMA flash attention, causal, GQA. Q-tile 128 rows, KV-tile 64.
// 8 warps; warp owns 16 full rows (FA-2, warp-local softmax).
// Softmax exp computed with packed f32x2 FMA (mask sentinel -500 keeps the
// unclamped packed exp2 in-range). 1D grid in LPT (longest-first) order.
// ---------------------------------------------------------------------------
#define FK_ROW  144
#define FK_TILE (64 * FK_ROW)
#define FQ_SZ   (128 * FK_ROW)
#define FK_SMEM (FQ_SZ + 2 * 2 * FK_TILE)      // 55296 B
#define N_QT    (S_LEN / 128)                  // 16

__global__ __launch_bounds__(256) void flash_hmma_kernel(
    const __half* __restrict__ qkvh, __half* __restrict__ Y)
{
    extern __shared__ char sm[];
    const uint32_t sb = smem_to_u32(sm);

    const int bx = blockIdx.x;
    const int qt = (N_QT - 1) - (bx >> 5);     // longest-first
    const int h  = bx & 31;
    const int kh = h >> 2;
    const int q0 = qt * 128;
    const int njt = 2 * qt + 2;

    const int tid  = threadIdx.x;
    const int w    = tid >> 5;
    const int lane = tid & 31;

    const float C2 = 0.18033688011112042f;   // (1/8) * log2(e)

    // packed-exp constants (pure, hoisted once)
    const u64 kMAG  = dup2(12582912.0f);
    const u64 kNMAG = dup2(-12582912.0f);
    const u64 kNEG1 = dup2(-1.0f);
    const u64 kONE  = dup2(1.0f);
    const u64 kC1   = dup2(6.9314718056e-1f);
    const u64 kC2   = dup2(2.4022650696e-1f);
    const u64 kC3   = dup2(5.5504108664e-2f);
    const u64 kC4   = dup2(9.6181291e-3f);
    const u64 kSC   = dup2(C2);

    const uint32_t qAddr = (uint32_t)(w * 16 + (lane & 15)) * FK_ROW + (lane >> 4) * 16;
    const uint32_t kAddr = (uint32_t)(((lane >> 4) & 1) * 8 + (lane & 7)) * FK_ROW
                           + ((lane >> 3) & 1) * 16;
    const uint32_t vAddr = (uint32_t)((lane & 7) + ((lane >> 3) & 1) * 8) * FK_ROW
                           + (lane >> 4) * 16;

    auto load_q = [&]() {
#pragma unroll
        for (int i = 0; i < 4; i++) {
            int p = tid + i * 256, row = p >> 3, ch = p & 7;
            cp_async16(sb + (uint32_t)row * FK_ROW + ch * 16,
                       qkvh + (size_t)(q0 + row) * QKV_COLS + h * HD + ch * 8);
        }
    };
    auto load_kv = [&](int s, int jt) {
        const int j0 = jt * 64;
        const uint32_t Kb = sb + FQ_SZ + s * 2 * FK_TILE;
#pragma unroll
        for (int i = 0; i < 2; i++) {
            int p = tid + i * 256, row = p >> 3, ch = p & 7;
            const __half* base = qkvh + (size_t)(j0 + row) * QKV_COLS + kh * HD + ch * 8;
            cp_async16(Kb + (uint32_t)row * FK_ROW + ch * 16, base + NH * HD);
            cp_async16(Kb + FK_TILE + (uint32_t)row * FK_ROW + ch * 16, base + (NH + NKV) * HD);
        }
    };

    load_q(); load_kv(0, 0); cp_commit();
    load_kv(1, 1); cp_commit();

    uint32_t aQ[4][4];
    float o[8][4];
#pragma unroll
    for (int n = 0; n < 8; n++)
#pragma unroll
        for (int q = 0; q < 4; q++) o[n][q] = 0.f;
    float m2[2] = { -1e30f, -1e30f };
    float l[2]  = { 0.f, 0.f };

    for (int jt = 0; jt < njt; jt++) {
        cp_wait1();
        __syncthreads();
        if (jt == 0) {
#pragma unroll
            for (int kc = 0; kc < 4; kc++) ldsm4(aQ[kc], sb + qAddr + kc * 32);
        }

        const uint32_t Kb = sb + FQ_SZ + (jt & 1) * 2 * FK_TILE;
        const uint32_t Vb = Kb + FK_TILE;

        float sc[8][4];
#pragma unroll
        for (int n = 0; n < 8; n++)
#pragma unroll
            for (int q = 0; q < 4; q++) sc[n][q] = 0.f;
#pragma unroll
        for (int p = 0; p < 4; p++) {
#pragma unroll
            for (int kc = 0; kc < 4; kc++) {
                uint32_t b[4];
                ldsm4(b, Kb + kAddr + (uint32_t)p * 16 * FK_ROW + kc * 32);
                mma16816f16(sc[2 * p + 0], aQ[kc], b + 0);
                mma16816f16(sc[2 * p + 1], aQ[kc], b + 2);
            }
        }

        // causal mask. Sentinel -500: raw |scores| <~ 200, so it is strictly
        // dominated, exp2 arg stays in [-126, 0], and 2^arg is exactly 0.0f
        // relative to row max (2^-90 range).
        if (jt >= 2 * qt) {
            const int j0 = jt * 64;
            const int rg = q0 + w * 16 + (lane >> 2);
            const int cb = j0 + (lane & 3) * 2;
#pragma unroll
            for (int n = 0; n < 8; n++) {
#pragma unroll
                for (int e = 0; e < 2; e++) {
                    int cg = cb + n * 8 + e;
                    if (cg > rg)     sc[n][e]     = -500.f;
                    if (cg > rg + 8) sc[n][e + 2] = -500.f;
                }
            }
        }

        // online softmax (log2 domain), packed-pair exp
        uint32_t ph[8][2];
#pragma unroll
        for (int i = 0; i < 2; i++) {
            float mr = -1e30f;
#pragma unroll
            for (int n = 0; n < 8; n++)
                mr = fmaxf(mr, fmaxf(sc[n][2 * i], sc[n][2 * i + 1]));
            mr = fmaxf(mr, __shfl_xor_sync(0xffffffffu, mr, 1));
            mr = fmaxf(mr, __shfl_xor_sync(0xffffffffu, mr, 2));
            float m2n = fmaxf(m2[i], mr * C2);
            float r = fexp2(m2[i] - m2n);      // scalar, clamped (m2 init -1e30)
            m2[i] = m2n;
            const u64 NM2 = dup2(-m2n);
            float sum = 0.f;
#pragma unroll
            for (int n = 0; n < 8; n++) {
                u64 s2  = pk2(sc[n][2 * i], sc[n][2 * i + 1]);
                u64 arg = fma2_(s2, kSC, NM2);
                float p0, p1;
                FEXP2X2(arg, p0, p1);
                sum += p0 + p1;
                ph[n][i] = pack_h2(p0, p1);
            }
            sum += __shfl_xor_sync(0xffffffffu, sum, 1);
            sum += __shfl_xor_sync(0xffffffffu, sum, 2);
            l[i] = l[i] * r + sum;
#pragma unroll
            for (int n = 0; n < 8; n++) {
                o[n][2 * i]     *= r;
                o[n][2 * i + 1] *= r;
            }
        }

        // O += P @ V
#pragma unroll
        for (int kc = 0; kc < 4; kc++) {
            uint32_t a[4] = { ph[2 * kc][0], ph[2 * kc][1],
                              ph[2 * kc + 1][0], ph[2 * kc + 1][1] };
#pragma unroll
            for (int vp = 0; vp < 4; vp++) {
                uint32_t b[4];
                ldsm4t(b, Vb + vAddr + (uint32_t)kc * 16 * FK_ROW + vp * 32);
                mma16816f16(o[2 * vp + 0], a, b + 0);
                mma16816f16(o[2 * vp + 1], a, b + 2);
            }
        }

        __syncthreads();
        if (jt + 2 < njt) load_kv(jt & 1, jt + 2);
        cp_commit();
    }

    // epilogue: fp16 y
#pragma unroll
    for (int i = 0; i < 2; i++) {
        float inv = 1.f / l[i];
        int row = q0 + w * 16 + (lane >> 2) + 8 * i;
        __half* yr = Y + (size_t)row * H_DIM + h * HD + (lane & 3) * 2;
#pragma unroll
        for (int n = 0; n < 8; n++) {
            __half2 v = __floats2half2_rn(o[n][2 * i] * inv, o[n][2 * i + 1] * inv);
            *reinterpret_cast<__half2*>(yr + n * 8) = v;
        }
    }
}

// ---------------------------------------------------------------------------
// kernel_launch: 4 launches total
// ---------------------------------------------------------------------------
extern "C" void kernel_launch(void* const* d_in, const int* in_sizes, int n_in,
                              void* d_out, int out_size)
{
    const float* x    = (const float*)d_in[0];
    const float* fc   = (const float*)d_in[1];
    const float* Wqkv = (const float*)d_in[3];
    const float* Wo   = (const float*)d_in[4];
    float* out = (float*)d_out;

    __half *qkvh, *ga, *gb, *gc;
    cudaGetSymbolAddress((void**)&qkvh, g_qkvh);
    cudaGetSymbolAddress((void**)&ga, g_a);
    cudaGetSymbolAddress((void**)&gb, g_b);
    cudaGetSymbolAddress((void**)&gc, g_c);

    cudaFuncSetAttribute((const void*)hgemm_kernel<true, true>,
                         cudaFuncAttributeMaxDynamicSharedMemorySize, HM_SMEM);
    cudaFuncSetAttribute((const void*)hgemm_kernel<false, false>,
                         cudaFuncAttributeMaxDynamicSharedMemorySize, HM_SMEM);
    cudaFuncSetAttribute((const void*)flash_hmma_kernel,
                         cudaFuncAttributeMaxDynamicSharedMemorySize, FK_SMEM);

    // 1) fused convert: x, Wqkv, Wo -> fp16
    cvt_all_kernel<<<(N4_ALL + 255) / 256, 256>>>(
        (const float4*)x, (const float4*)Wqkv, (const float4*)Wo,
        (uint2*)ga, (uint2*)gb, (uint2*)gc);

    // 2) QKV projection with fused RoPE, fp16 output
    {
        dim3 grid(QKV_COLS / 128, S_LEN / 128);
        hgemm_kernel<true, true><<<grid, 256, HM_SMEM>>>(
            ga, gb, qkvh, fc, S_LEN, QKV_COLS, H_DIM);
    }

    // 3) HMMA flash attention (q-tile 128, LPT order) -> g_a (fp16 y)
    flash_hmma_kernel<<<N_QT * NH, 256, FK_SMEM>>>(qkvh, ga);

    // 4) output projection, fp32 output: out = y @ Wo^T
    {
        dim3 grid(H_DIM / 128, S_LEN / 128);
        hgemm_kernel<false, false><<<grid, 256, HM_SMEM>>>(
            ga, gc, out, nullptr, S_LEN, H_DIM, H_DIM);
    }
}

// round 9
// speedup vs baseline: 8.0591x; 1.1187x over previous
#include <cuda_runtime.h>
#include <cuda_fp16.h>
#include <cstdint>

// Problem constants (fixed by the dataset)
#define S_LEN 2048
#define H_DIM 2048
#define NH    32
#define NKV   8
#define HD    64
#define QKV_COLS ((NH + 2*NKV) * HD)   // 3072

// ---------------------------------------------------------------------------
// Scratch (allocation-free rule: __device__ globals)
// ---------------------------------------------------------------------------
__device__ __align__(16) __half g_qkvh[(size_t)S_LEN * QKV_COLS]; // 12 MB
__device__ __align__(16) __half g_a[(size_t)S_LEN * H_DIM];       // 8 MB (x, then y)
__device__ __align__(16) __half g_b[(size_t)QKV_COLS * H_DIM];    // 12 MB (Wqkv)
__device__ __align__(16) __half g_c[(size_t)H_DIM * H_DIM];       // 8 MB (Wo)

// ---------------------------------------------------------------------------
// Arch-agnostic PTX helpers (sm_80+ ISA; tcgen05 rejected by plain-sm_103 ptxas)
// ---------------------------------------------------------------------------
__device__ __forceinline__ uint32_t smem_to_u32(const void* p) {
    uint32_t a;
    asm("{ .reg .u64 t; cvta.to.shared.u64 t, %1; cvt.u32.u64 %0, t; }"
        : "=r"(a) : "l"(p));
    return a;
}
__device__ __forceinline__ void cp_async16(uint32_t smem, const void* gptr) {
    asm volatile("cp.async.cg.shared.global [%0], [%1], 16;"
                 :: "r"(smem), "l"(__cvta_generic_to_global(gptr)) : "memory");
}
__device__ __forceinline__ void cp_commit() {
    asm volatile("cp.async.commit_group;" ::: "memory");
}
__device__ __forceinline__ void cp_wait1() {
    asm volatile("cp.async.wait_group 1;" ::: "memory");
}
__device__ __forceinline__ void ldsm4(uint32_t* r, uint32_t addr) {
    asm volatile("ldmatrix.sync.aligned.m8n8.x4.shared.b16 {%0,%1,%2,%3}, [%4];"
                 : "=r"(r[0]), "=r"(r[1]), "=r"(r[2]), "=r"(r[3]) : "r"(addr));
}
__device__ __forceinline__ void ldsm4t(uint32_t* r, uint32_t addr) {
    asm volatile("ldmatrix.sync.aligned.m8n8.x4.trans.shared.b16 {%0,%1,%2,%3}, [%4];"
                 : "=r"(r[0]), "=r"(r[1]), "=r"(r[2]), "=r"(r[3]) : "r"(addr));
}
__device__ __forceinline__ void mma16816f16(float* c, const uint32_t* a, const uint32_t* b) {
    asm volatile(
        "mma.sync.aligned.m16n8k16.row.col.f32.f16.f16.f32 "
        "{%0,%1,%2,%3}, {%4,%5,%6,%7}, {%8,%9}, {%0,%1,%2,%3};"
        : "+f"(c[0]), "+f"(c[1]), "+f"(c[2]), "+f"(c[3])
        : "r"(a[0]), "r"(a[1]), "r"(a[2]), "r"(a[3]), "r"(b[0]), "r"(b[1]));
}
__device__ __forceinline__ uint32_t pack_h2(float a, float b) {
    __half2 h = __floats2half2_rn(a, b);
    return *reinterpret_cast<uint32_t*>(&h);
}

// ---- packed f32x2 ops (Blackwell base ISA) ----
typedef unsigned long long u64;
__device__ __forceinline__ u64 pk2(float a, float b) {
    u64 r; asm("mov.b64 %0, {%1, %2};" : "=l"(r) : "f"(a), "f"(b)); return r;
}
__device__ __forceinline__ void upk2(u64 v, float& a, float& b) {
    asm("mov.b64 {%0, %1}, %2;" : "=f"(a), "=f"(b) : "l"(v));
}
__device__ __forceinline__ u64 add2_(u64 a, u64 b) {
    u64 r; asm("add.rn.f32x2 %0, %1, %2;" : "=l"(r) : "l"(a), "l"(b)); return r;
}
__device__ __forceinline__ u64 fma2_(u64 a, u64 b, u64 c) {
    u64 r; asm("fma.rn.f32x2 %0, %1, %2, %3;" : "=l"(r) : "l"(a), "l"(b), "l"(c)); return r;
}
__device__ __forceinline__ u64 dup2(float x) {
    unsigned int b = __float_as_uint(x);
    return ((u64)b << 32) | b;
}

// Scalar fast 2^d (clamped; used only for the per-pass rescale factor).
__device__ __forceinline__ float fexp2(float d) {
    d = fmaxf(d, -80.0f);
    float t  = d + 12582912.0f;
    float nf = t - 12582912.0f;
    float f  = d - nf;
    int   n  = __float_as_int(t) - 0x4B400000;
    float p  = 9.6181291e-3f;
    p = fmaf(p, f, 5.5504108664e-2f);
    p = fmaf(p, f, 2.4022650696e-1f);
    p = fmaf(p, f, 6.9314718056e-1f);
    p = fmaf(p, f, 1.0f);
    return __int_as_float(__float_as_int(p) + (n << 23));
}

// Packed 2^(a0), 2^(a1). Args MUST be in [-126, 0] (guaranteed by the -500
// mask sentinel and score bounds) — no clamp, deg-4 poly (~4e-5 rel err).
// Constants are materialized locally (short live ranges).
#define FEXP2X2(arg, r0, r1) do {                                           \
    const u64 _kMAG  = dup2(12582912.0f);                                   \
    const u64 _kNEG1 = dup2(-1.0f);                                         \
    u64 _t  = add2_(arg, _kMAG);                                            \
    u64 _nf = add2_(_t, dup2(-12582912.0f));                                \
    u64 _f  = fma2_(_nf, _kNEG1, arg);                                      \
    u64 _p  = fma2_(dup2(9.6181291e-3f), _f, dup2(5.5504108664e-2f));       \
    _p = fma2_(_p, _f, dup2(2.4022650696e-1f));                             \
    _p = fma2_(_p, _f, dup2(6.9314718056e-1f));                             \
    _p = fma2_(_p, _f, dup2(1.0f));                                         \
    float _t0, _t1, _p0, _p1;                                               \
    upk2(_t, _t0, _t1);                                                     \
    upk2(_p, _p0, _p1);                                                     \
    int _n0 = (__float_as_int(_t0) - 0x4B400000) << 23;                     \
    int _n1 = (__float_as_int(_t1) - 0x4B400000) << 23;                     \
    r0 = __int_as_float(__float_as_int(_p0) + _n0);                         \
    r1 = __int_as_float(__float_as_int(_p1) + _n1);                         \
} while (0)

// ---------------------------------------------------------------------------
// Fused fp32 -> fp16 convert for x, Wqkv, Wo in one launch
// ---------------------------------------------------------------------------
#define N4_X  (S_LEN * H_DIM / 4)
#define N4_WQ (QKV_COLS * H_DIM / 4)
#define N4_WO (H_DIM * H_DIM / 4)
#define N4_ALL (N4_X + N4_WQ + N4_WO)

__global__ __launch_bounds__(256) void cvt_all_kernel(
    const float4* __restrict__ x, const float4* __restrict__ wq,
    const float4* __restrict__ wo,
    uint2* __restrict__ ox, uint2* __restrict__ owq, uint2* __restrict__ owo)
{
    int i = blockIdx.x * blockDim.x + threadIdx.x;
    const float4* in;
    uint2* out;
    int j;
    if (i < N4_X)                { in = x;  out = ox;  j = i; }
    else if (i < N4_X + N4_WQ)   { in = wq; out = owq; j = i - N4_X; }
    else if (i < N4_ALL)         { in = wo; out = owo; j = i - N4_X - N4_WQ; }
    else return;
    float4 f = in[j];
    out[j] = make_uint2(pack_h2(f.x, f.y), pack_h2(f.z, f.w));
}

// ---------------------------------------------------------------------------
// HMMA TN GEMM, fp16 in, templated output (fp32/fp16) + optional fused RoPE.
// CTA 128x128, BK=64, 3-stage cp.async pipeline: ONE sync + ONE wait per
// 64-wide chunk (was per 32-wide), loads issued before compute.
// Rows padded to 144 B (9 * 16B, odd -> conflict-free ldmatrix).
// ---------------------------------------------------------------------------
#define HM_ROWB   144
#define HM_TILE_B (128 * HM_ROWB)            // 18432 B
#define HM_STAGE  (2 * HM_TILE_B)            // 36864 B
#define HM_SMEM   (3 * HM_STAGE)             // 110592 B

template <bool HALF_OUT, bool ROPE>
__global__ __launch_bounds__(256, 2) void hgemm_kernel(
    const __half* __restrict__ A, const __half* __restrict__ B,
    void* __restrict__ Cv, const float* __restrict__ fc, int M, int N, int K)
{
    extern __shared__ char smem[];
    const uint32_t sbase = smem_to_u32(smem);

    const int tid  = threadIdx.x;
    const int wid  = tid >> 5;
    const int lane = tid & 31;
    const int warpM = wid >> 1;
    const int warpN = wid & 1;
    const int bm = blockIdx.y * 128;
    const int bn = blockIdx.x * 128;

    // cp.async geometry: row = tid>>3 (0..31) + 32*i, 16B chunk = (tid&7)
    const int ldrow = tid >> 3;
    const int ldch  = (tid & 7) * 16;
    const __half* gA0 = A + (size_t)(bm + ldrow) * K + (ldch >> 1);
    const __half* gB0 = B + (size_t)(bn + ldrow) * K + (ldch >> 1);

    const uint32_t aAddrBase =
        (uint32_t)(warpM * 32 + (lane & 15)) * HM_ROWB + (lane >> 4) * 16;
    const uint32_t bAddrBase =
        (uint32_t)(warpN * 64 + ((lane >> 4) & 1) * 8 + (lane & 7)) * HM_ROWB
        + ((lane >> 3) & 1) * 16;

    float acc[2][8][4];
#pragma unroll
    for (int m = 0; m < 2; m++)
#pragma unroll
        for (int n = 0; n < 8; n++)
#pragma unroll
            for (int q = 0; q < 4; q++) acc[m][n][q] = 0.f;

    const int nchunk = K / 64;               // 32

    auto load_stage = [&](int s, int c) {
        const uint32_t st = sbase + s * HM_STAGE;
        const int k0 = c * 64;
#pragma unroll
        for (int i = 0; i < 4; i++) {
            const uint32_t so = (uint32_t)(ldrow + 32 * i) * HM_ROWB + ldch;
            cp_async16(st + so, gA0 + (size_t)(32 * i) * K + k0);
            cp_async16(st + HM_TILE_B + so, gB0 + (size_t)(32 * i) * K + k0);
        }
    };

    // prologue: 2 chunks in flight
    load_stage(0, 0); cp_commit();
    load_stage(1, 1); cp_commit();

    int s = 0;                                // stage of chunk c
    for (int c = 0; c < nchunk; c++) {
        cp_wait1();               // chunk c arrived (1 group may stay pending)
        __syncthreads();          // stage data visible; chunk c-1 compute done
        {
            int s2 = s + 2; if (s2 >= 3) s2 -= 3;
            if (c + 2 < nchunk) load_stage(s2, c + 2);
            cp_commit();
        }

        const uint32_t st = sbase + s * HM_STAGE;
        const uint32_t sA = st + aAddrBase;
        const uint32_t sB = st + HM_TILE_B + bAddrBase;

#pragma unroll
        for (int ks = 0; ks < 4; ks++) {
            const uint32_t ko = ks * 32;
            uint32_t a[2][4];
            ldsm4(a[0], sA + ko);
            ldsm4(a[1], sA + 16 * HM_ROWB + ko);
#pragma unroll
            for (int p = 0; p < 4; p++) {
                uint32_t b[4];
                ldsm4(b, sB + (uint32_t)p * 16 * HM_ROWB + ko);
#pragma unroll
                for (int m = 0; m < 2; m++) {
                    mma16816f16(acc[m][2 * p + 0], a[m], b + 0);
                    mma16816f16(acc[m][2 * p + 1], a[m], b + 2);
                }
            }
        }
        if (++s == 3) s = 0;
    }

    // fused RoPE (uniform per CTA: q/k head cols are [0,2560), 128-aligned)
    if (ROPE && bn < NH * HD + NKV * HD) {
        const int d0 = lane & 3;
#pragma unroll
        for (int m = 0; m < 2; m++) {
            const int r0 = bm + warpM * 32 + m * 16 + (lane >> 2);
#pragma unroll
            for (int n = 0; n < 8; n++) {
                const int d = n * 4 + d0;
                float2 cs0 = *reinterpret_cast<const float2*>(fc + (size_t)r0 * 64 + d * 2);
                float2 cs1 = *reinterpret_cast<const float2*>(fc + (size_t)(r0 + 8) * 64 + d * 2);
                float x0 = acc[m][n][0], x1 = acc[m][n][1];
                acc[m][n][0] = x0 * cs0.x - x1 * cs0.y;
                acc[m][n][1] = x1 * cs0.x + x0 * cs0.y;
                float y0 = acc[m][n][2], y1 = acc[m][n][3];
                acc[m][n][2] = y0 * cs1.x - y1 * cs1.y;
                acc[m][n][3] = y1 * cs1.x + y0 * cs1.y;
            }
        }
    }

    const int qrow = lane >> 2;
    const int qcol = (lane & 3) * 2;
#pragma unroll
    for (int m = 0; m < 2; m++) {
        const int row0 = bm + warpM * 32 + m * 16 + qrow;
#pragma unroll
        for (int n = 0; n < 8; n++) {
            const int col = bn + warpN * 64 + n * 8 + qcol;
            if (HALF_OUT) {
                __half* C = (__half*)Cv;
                *reinterpret_cast<uint32_t*>(C + (size_t)row0 * N + col) =
                    pack_h2(acc[m][n][0], acc[m][n][1]);
                *reinterpret_cast<uint32_t*>(C + (size_t)(row0 + 8) * N + col) =
                    pack_h2(acc[m][n][2], acc[m][n][3]);
            } else {
                float* C = (float*)Cv;
                *reinterpret_cast<float2*>(C + (size_t)row0 * N + col) =
                    make_float2(acc[m][n][0], acc[m][n][1]);
                *reinterpret_cast<float2*>(C + (size_t)(row0 + 8) * N + col) =
                    make_float2(acc[m][n][2], acc[m][n][3]);
            }
        }
    }
}

// ---------------------------------------------------------------------------
// HMMA flash attention, causal, GQA. Q-tile 128 rows, KV-tile 64.
// 8 warps, warp owns 16 full rows (FA-2, warp-local softmax).
// 3 KV stages: ONE sync + ONE wait per tile, loads issued pre-compute,
// prefetch distance 2 tiles. LPT (longest-first) 1D grid.
// ---------------------------------------------------------------------------
#define FK_ROW  144
#define FK_TILE (64 * FK_ROW)                  // 9216 B
#define FQ_SZ   (128 * FK_ROW)                 // 18432 B
#define FK_STG  (2 * FK_TILE)                  // K+V stage: 18432 B
#define FK_SMEM (FQ_SZ + 3 * FK_STG)           // 73728 B
#define N_QT    (S_LEN / 128)                  // 16

__global__ __launch_bounds__(256, 2) void flash_hmma_kernel(
    const __half* __restrict__ qkvh, __half* __restrict__ Y)
{
    extern __shared__ char sm[];
    const uint32_t sb = smem_to_u32(sm);

    const int bx = blockIdx.x;
    const int qt = (N_QT - 1) - (bx >> 5);     // longest-first
    const int h  = bx & 31;
    const int kh = h >> 2;
    const int q0 = qt * 128;
    const int njt = 2 * qt + 2;                // >= 2 always

    const int tid  = threadIdx.x;
    const int w    = tid >> 5;
    const int lane = tid & 31;

    const float C2 = 0.18033688011112042f;   // (1/8) * log2(e)

    const uint32_t qAddr = (uint32_t)(w * 16 + (lane & 15)) * FK_ROW + (lane >> 4) * 16;
    const uint32_t kAddr = (uint32_t)(((lane >> 4) & 1) * 8 + (lane & 7)) * FK_ROW
                           + ((lane >> 3) & 1) * 16;
    const uint32_t vAddr = (uint32_t)((lane & 7) + ((lane >> 3) & 1) * 8) * FK_ROW
                           + (lane >> 4) * 16;

    auto load_q = [&]() {
#pragma unroll
        for (int i = 0; i < 4; i++) {
            int p = tid + i * 256, row = p >> 3, ch = p & 7;
            cp_async16(sb + (uint32_t)row * FK_ROW + ch * 16,
                       qkvh + (size_t)(q0 + row) * QKV_COLS + h * HD + ch * 8);
        }
    };
    auto load_kv = [&](int s, int jt) {
        const int j0 = jt * 64;
        const uint32_t Kb = sb + FQ_SZ + s * FK_STG;
#pragma unroll
        for (int i = 0; i < 2; i++) {
            int p = tid + i * 256, row = p >> 3, ch = p & 7;
            const __half* base = qkvh + (size_t)(j0 + row) * QKV_COLS + kh * HD + ch * 8;
            cp_async16(Kb + (uint32_t)row * FK_ROW + ch * 16, base + NH * HD);
            cp_async16(Kb + FK_TILE + (uint32_t)row * FK_ROW + ch * 16, base + (NH + NKV) * HD);
        }
    };

    // prologue: Q + kv0 (group 0), kv1 (group 1)
    load_q(); load_kv(0, 0); cp_commit();
    load_kv(1, 1); cp_commit();

    uint32_t aQ[4][4];
    float o[8][4];
#pragma unroll
    for (int n = 0; n < 8; n++)
#pragma unroll
        for (int q = 0; q < 4; q++) o[n][q] = 0.f;
    float m2[2] = { -1e30f, -1e30f };
    float l[2]  = { 0.f, 0.f };

    int s = 0;                                 // stage of tile jt
    for (int jt = 0; jt < njt; jt++) {
        cp_wait1();               // tile jt arrived (1 group may stay pending)
        __syncthreads();          // visible; tile jt-1 compute done by all
        {
            int s2 = s + 2; if (s2 >= 3) s2 -= 3;
            if (jt + 2 < njt) load_kv(s2, jt + 2);
            cp_commit();
        }
        if (jt == 0) {
#pragma unroll
            for (int kc = 0; kc < 4; kc++) ldsm4(aQ[kc], sb + qAddr + kc * 32);
        }

        const uint32_t Kb = sb + FQ_SZ + s * FK_STG;
        const uint32_t Vb = Kb + FK_TILE;

        float sc[8][4];
#pragma unroll
        for (int n = 0; n < 8; n++)
#pragma unroll
            for (int q = 0; q < 4; q++) sc[n][q] = 0.f;
#pragma unroll
        for (int p = 0; p < 4; p++) {
#pragma unroll
            for (int kc = 0; kc < 4; kc++) {
                uint32_t b[4];
                ldsm4(b, Kb + kAddr + (uint32_t)p * 16 * FK_ROW + kc * 32);
                mma16816f16(sc[2 * p + 0], aQ[kc], b + 0);
                mma16816f16(sc[2 * p + 1], aQ[kc], b + 2);
            }
        }

        // causal mask (sentinel -500 keeps the unclamped packed exp2 in-range)
        if (jt >= 2 * qt) {
            const int j0 = jt * 64;
            const int rg = q0 + w * 16 + (lane >> 2);
            const int cb = j0 + (lane & 3) * 2;
#pragma unroll
            for (int n = 0; n < 8; n++) {
#pragma unroll
                for (int e = 0; e < 2; e++) {
                    int cg = cb + n * 8 + e;
                    if (cg > rg)     sc[n][e]     = -500.f;
                    if (cg > rg + 8) sc[n][e + 2] = -500.f;
                }
            }
        }

        // online softmax (log2 domain), packed-pair exp
        uint32_t ph[8][2];
#pragma unroll
        for (int i = 0; i < 2; i++) {
            float mr = -1e30f;
#pragma unroll
            for (int n = 0; n < 8; n++)
                mr = fmaxf(mr, fmaxf(sc[n][2 * i], sc[n][2 * i + 1]));
            mr = fmaxf(mr, __shfl_xor_sync(0xffffffffu, mr, 1));
            mr = fmaxf(mr, __shfl_xor_sync(0xffffffffu, mr, 2));
            float m2n = fmaxf(m2[i], mr * C2);
            float r = fexp2(m2[i] - m2n);      // scalar, clamped (m2 init -1e30)
            m2[i] = m2n;
            const u64 NM2 = dup2(-m2n);
            const u64 kSC = dup2(C2);
            float sum = 0.f;
#pragma unroll
            for (int n = 0; n < 8; n++) {
                u64 s2  = pk2(sc[n][2 * i], sc[n][2 * i + 1]);
                u64 arg = fma2_(s2, kSC, NM2);
                float p0, p1;
                FEXP2X2(arg, p0, p1);
                sum += p0 + p1;
                ph[n][i] = pack_h2(p0, p1);
            }
            sum += __shfl_xor_sync(0xffffffffu, sum, 1);
            sum += __shfl_xor_sync(0xffffffffu, sum, 2);
            l[i] = l[i] * r + sum;
#pragma unroll
            for (int n = 0; n < 8; n++) {
                o[n][2 * i]     *= r;
                o[n][2 * i + 1] *= r;
            }
        }

        // O += P @ V
#pragma unroll
        for (int kc = 0; kc < 4; kc++) {
            uint32_t a[4] = { ph[2 * kc][0], ph[2 * kc][1],
                              ph[2 * kc + 1][0], ph[2 * kc + 1][1] };
#pragma unroll
            for (int vp = 0; vp < 4; vp++) {
                uint32_t b[4];
                ldsm4t(b, Vb + vAddr + (uint32_t)kc * 16 * FK_ROW + vp * 32);
                mma16816f16(o[2 * vp + 0], a, b + 0);
                mma16816f16(o[2 * vp + 1], a, b + 2);
            }
        }

        if (++s == 3) s = 0;
    }

    // epilogue: fp16 y
#pragma unroll
    for (int i = 0; i < 2; i++) {
        float inv = 1.f / l[i];
        int row = q0 + w * 16 + (lane >> 2) + 8 * i;
        __half* yr = Y + (size_t)row * H_DIM + h * HD + (lane & 3) * 2;
#pragma unroll
        for (int n = 0; n < 8; n++) {
            __half2 v = __floats2half2_rn(o[n][2 * i] * inv, o[n][2 * i + 1] * inv);
            *reinterpret_cast<__half2*>(yr + n * 8) = v;
        }
    }
}

// ---------------------------------------------------------------------------
// kernel_launch: 4 launches total
// ---------------------------------------------------------------------------
extern "C" void kernel_launch(void* const* d_in, const int* in_sizes, int n_in,
                              void* d_out, int out_size)
{
    const float* x    = (const float*)d_in[0];
    const float* fc   = (const float*)d_in[1];
    const float* Wqkv = (const float*)d_in[3];
    const float* Wo   = (const float*)d_in[4];
    float* out = (float*)d_out;

    __half *qkvh, *ga, *gb, *gc;
    cudaGetSymbolAddress((void**)&qkvh, g_qkvh);
    cudaGetSymbolAddress((void**)&ga, g_a);
    cudaGetSymbolAddress((void**)&gb, g_b);
    cudaGetSymbolAddress((void**)&gc, g_c);

    cudaFuncSetAttribute((const void*)hgemm_kernel<true, true>,
                         cudaFuncAttributeMaxDynamicSharedMemorySize, HM_SMEM);
    cudaFuncSetAttribute((const void*)hgemm_kernel<false, false>,
                         cudaFuncAttributeMaxDynamicSharedMemorySize, HM_SMEM);
    cudaFuncSetAttribute((const void*)flash_hmma_kernel,
                         cudaFuncAttributeMaxDynamicSharedMemorySize, FK_SMEM);

    // 1) fused convert: x, Wqkv, Wo -> fp16
    cvt_all_kernel<<<(N4_ALL + 255) / 256, 256>>>(
        (const float4*)x, (const float4*)Wqkv, (const float4*)Wo,
        (uint2*)ga, (uint2*)gb, (uint2*)gc);

    // 2) QKV projection with fused RoPE, fp16 output
    {
        dim3 grid(QKV_COLS / 128, S_LEN / 128);
        hgemm_kernel<true, true><<<grid, 256, HM_SMEM>>>(
            ga, gb, qkvh, fc, S_LEN, QKV_COLS, H_DIM);
    }

    // 3) HMMA flash attention (q-tile 128, LPT order) -> g_a (fp16 y)
    flash_hmma_kernel<<<N_QT * NH, 256, FK_SMEM>>>(qkvh, ga);

    // 4) output projection, fp32 output: out = y @ Wo^T
    {
        dim3 grid(H_DIM / 128, S_LEN / 128);
        hgemm_kernel<false, false><<<grid, 256, HM_SMEM>>>(
            ga, gc, out, nullptr, S_LEN, H_DIM, H_DIM);
    }
}

// round 10
// speedup vs baseline: 8.1258x; 1.0083x over previous
#include <cuda_runtime.h>
#include <cuda_fp16.h>
#include <cstdint>

// Problem constants (fixed by the dataset)
#define S_LEN 2048
#define H_DIM 2048
#define NH    32
#define NKV   8
#define HD    64
#define QKV_COLS ((NH + 2*NKV) * HD)   // 3072

// ---------------------------------------------------------------------------
// Scratch (allocation-free rule: __device__ globals)
// ---------------------------------------------------------------------------
__device__ __align__(16) __half g_qkvh[(size_t)S_LEN * QKV_COLS]; // 12 MB
__device__ __align__(16) __half g_a[(size_t)S_LEN * H_DIM];       // 8 MB (x, then y)
__device__ __align__(16) __half g_b[(size_t)QKV_COLS * H_DIM];    // 12 MB (Wqkv)
__device__ __align__(16) __half g_c[(size_t)H_DIM * H_DIM];       // 8 MB (Wo)

// ---------------------------------------------------------------------------
// Arch-agnostic PTX helpers (sm_80+ ISA; tcgen05 rejected by plain-sm_103 ptxas)
// ---------------------------------------------------------------------------
__device__ __forceinline__ uint32_t smem_to_u32(const void* p) {
    uint32_t a;
    asm("{ .reg .u64 t; cvta.to.shared.u64 t, %1; cvt.u32.u64 %0, t; }"
        : "=r"(a) : "l"(p));
    return a;
}
__device__ __forceinline__ void cp_async16(uint32_t smem, const void* gptr) {
    asm volatile("cp.async.cg.shared.global [%0], [%1], 16;"
                 :: "r"(smem), "l"(__cvta_generic_to_global(gptr)) : "memory");
}
__device__ __forceinline__ void cp_commit() {
    asm volatile("cp.async.commit_group;" ::: "memory");
}
__device__ __forceinline__ void cp_wait1() {
    asm volatile("cp.async.wait_group 1;" ::: "memory");
}
__device__ __forceinline__ void ldsm4(uint32_t* r, uint32_t addr) {
    asm volatile("ldmatrix.sync.aligned.m8n8.x4.shared.b16 {%0,%1,%2,%3}, [%4];"
                 : "=r"(r[0]), "=r"(r[1]), "=r"(r[2]), "=r"(r[3]) : "r"(addr));
}
__device__ __forceinline__ void ldsm4t(uint32_t* r, uint32_t addr) {
    asm volatile("ldmatrix.sync.aligned.m8n8.x4.trans.shared.b16 {%0,%1,%2,%3}, [%4];"
                 : "=r"(r[0]), "=r"(r[1]), "=r"(r[2]), "=r"(r[3]) : "r"(addr));
}
__device__ __forceinline__ void mma16816f16(float* c, const uint32_t* a, const uint32_t* b) {
    asm volatile(
        "mma.sync.aligned.m16n8k16.row.col.f32.f16.f16.f32 "
        "{%0,%1,%2,%3}, {%4,%5,%6,%7}, {%8,%9}, {%0,%1,%2,%3};"
        : "+f"(c[0]), "+f"(c[1]), "+f"(c[2]), "+f"(c[3])
        : "r"(a[0]), "r"(a[1]), "r"(a[2]), "r"(a[3]), "r"(b[0]), "r"(b[1]));
}
__device__ __forceinline__ uint32_t pack_h2(float a, float b) {
    __half2 h = __floats2half2_rn(a, b);
    return *reinterpret_cast<uint32_t*>(&h);
}

// ---- packed f32x2 ops (Blackwell base ISA) ----
typedef unsigned long long u64;
__device__ __forceinline__ u64 pk2(float a, float b) {
    u64 r; asm("mov.b64 %0, {%1, %2};" : "=l"(r) : "f"(a), "f"(b)); return r;
}
__device__ __forceinline__ void upk2(u64 v, float& a, float& b) {
    asm("mov.b64 {%0, %1}, %2;" : "=f"(a), "=f"(b) : "l"(v));
}
__device__ __forceinline__ u64 add2_(u64 a, u64 b) {
    u64 r; asm("add.rn.f32x2 %0, %1, %2;" : "=l"(r) : "l"(a), "l"(b)); return r;
}
__device__ __forceinline__ u64 fma2_(u64 a, u64 b, u64 c) {
    u64 r; asm("fma.rn.f32x2 %0, %1, %2, %3;" : "=l"(r) : "l"(a), "l"(b), "l"(c)); return r;
}
__device__ __forceinline__ u64 dup2(float x) {
    unsigned int b = __float_as_uint(x);
    return ((u64)b << 32) | b;
}

// Scalar fast 2^d (clamped; used only for the per-pass rescale factor).
__device__ __forceinline__ float fexp2(float d) {
    d = fmaxf(d, -80.0f);
    float t  = d + 12582912.0f;
    float nf = t - 12582912.0f;
    float f  = d - nf;
    int   n  = __float_as_int(t) - 0x4B400000;
    float p  = 9.6181291e-3f;
    p = fmaf(p, f, 5.5504108664e-2f);
    p = fmaf(p, f, 2.4022650696e-1f);
    p = fmaf(p, f, 6.9314718056e-1f);
    p = fmaf(p, f, 1.0f);
    return __int_as_float(__float_as_int(p) + (n << 23));
}

// Packed 2^(a0), 2^(a1). Args MUST be in [-126, 0] (guaranteed by the -500
// mask sentinel and score bounds) — no clamp, deg-4 poly (~4e-5 rel err).
#define FEXP2X2(arg, r0, r1) do {                                           \
    const u64 _kMAG  = dup2(12582912.0f);                                   \
    const u64 _kNEG1 = dup2(-1.0f);                                         \
    u64 _t  = add2_(arg, _kMAG);                                            \
    u64 _nf = add2_(_t, dup2(-12582912.0f));                                \
    u64 _f  = fma2_(_nf, _kNEG1, arg);                                      \
    u64 _p  = fma2_(dup2(9.6181291e-3f), _f, dup2(5.5504108664e-2f));       \
    _p = fma2_(_p, _f, dup2(2.4022650696e-1f));                             \
    _p = fma2_(_p, _f, dup2(6.9314718056e-1f));                             \
    _p = fma2_(_p, _f, dup2(1.0f));                                         \
    float _t0, _t1, _p0, _p1;                                               \
    upk2(_t, _t0, _t1);                                                     \
    upk2(_p, _p0, _p1);                                                     \
    int _n0 = (__float_as_int(_t0) - 0x4B400000) << 23;                     \
    int _n1 = (__float_as_int(_t1) - 0x4B400000) << 23;                     \
    r0 = __int_as_float(__float_as_int(_p0) + _n0);                         \
    r1 = __int_as_float(__float_as_int(_p1) + _n1);                         \
} while (0)

// ---------------------------------------------------------------------------
// Fused fp32 -> fp16 convert for x, Wqkv, Wo. 4 float4 per thread (ILP 4);
// all three array boundaries are multiples of the 1024-elem block chunk, so
// array selection is uniform per block.
// ---------------------------------------------------------------------------
#define N4_X  (S_LEN * H_DIM / 4)        // 1048576
#define N4_WQ (QKV_COLS * H_DIM / 4)     // 1572864
#define N4_WO (H_DIM * H_DIM / 4)        // 1048576
#define N4_ALL (N4_X + N4_WQ + N4_WO)    // 3670016
#define CVT_BLOCKS (N4_ALL / 1024)       // 3584

__global__ __launch_bounds__(256) void cvt_all_kernel(
    const float4* __restrict__ x, const float4* __restrict__ wq,
    const float4* __restrict__ wo,
    uint2* __restrict__ ox, uint2* __restrict__ owq, uint2* __restrict__ owo)
{
    const size_t base = (size_t)blockIdx.x * 1024;
    const float4* in;
    uint2* out;
    size_t j0;
    if (base < N4_X)              { in = x;  out = ox;  j0 = base; }
    else if (base < (size_t)N4_X + N4_WQ) { in = wq; out = owq; j0 = base - N4_X; }
    else                          { in = wo; out = owo; j0 = base - N4_X - N4_WQ; }

    const size_t t = j0 + threadIdx.x;
    float4 f0 = in[t];
    float4 f1 = in[t + 256];
    float4 f2 = in[t + 512];
    float4 f3 = in[t + 768];
    out[t]       = make_uint2(pack_h2(f0.x, f0.y), pack_h2(f0.z, f0.w));
    out[t + 256] = make_uint2(pack_h2(f1.x, f1.y), pack_h2(f1.z, f1.w));
    out[t + 512] = make_uint2(pack_h2(f2.x, f2.y), pack_h2(f2.z, f2.w));
    out[t + 768] = make_uint2(pack_h2(f3.x, f3.y), pack_h2(f3.z, f3.w));
}

// ---------------------------------------------------------------------------
// HMMA TN GEMM, fp16 in, templated output (fp32/fp16) + optional fused RoPE.
// CTA 128x128, BK=64, 3-stage cp.async pipeline, ONE sync + ONE wait/chunk.
// Inner loop: b-fragment double buffer — ldsm for micro-tile p+1 issued
// before the mma of p (hides LDS latency without blowing the 128-reg cap).
// ---------------------------------------------------------------------------
#define HM_ROWB   144
#define HM_TILE_B (128 * HM_ROWB)            // 18432 B
#define HM_STAGE  (2 * HM_TILE_B)            // 36864 B
#define HM_SMEM   (3 * HM_STAGE)             // 110592 B

template <bool HALF_OUT, bool ROPE>
__global__ __launch_bounds__(256, 2) void hgemm_kernel(
    const __half* __restrict__ A, const __half* __restrict__ B,
    void* __restrict__ Cv, const float* __restrict__ fc, int M, int N, int K)
{
    extern __shared__ char smem[];
    const uint32_t sbase = smem_to_u32(smem);

    const int tid  = threadIdx.x;
    const int wid  = tid >> 5;
    const int lane = tid & 31;
    const int warpM = wid >> 1;
    const int warpN = wid & 1;
    const int bm = blockIdx.y * 128;
    const int bn = blockIdx.x * 128;

    const int ldrow = tid >> 3;
    const int ldch  = (tid & 7) * 16;
    const __half* gA0 = A + (size_t)(bm + ldrow) * K + (ldch >> 1);
    const __half* gB0 = B + (size_t)(bn + ldrow) * K + (ldch >> 1);

    const uint32_t aAddrBase =
        (uint32_t)(warpM * 32 + (lane & 15)) * HM_ROWB + (lane >> 4) * 16;
    const uint32_t bAddrBase =
        (uint32_t)(warpN * 64 + ((lane >> 4) & 1) * 8 + (lane & 7)) * HM_ROWB
        + ((lane >> 3) & 1) * 16;

    float acc[2][8][4];
#pragma unroll
    for (int m = 0; m < 2; m++)
#pragma unroll
        for (int n = 0; n < 8; n++)
#pragma unroll
            for (int q = 0; q < 4; q++) acc[m][n][q] = 0.f;

    const int nchunk = K / 64;               // 32

    auto load_stage = [&](int s, int c) {
        const uint32_t st = sbase + s * HM_STAGE;
        const int k0 = c * 64;
#pragma unroll
        for (int i = 0; i < 4; i++) {
            const uint32_t so = (uint32_t)(ldrow + 32 * i) * HM_ROWB + ldch;
            cp_async16(st + so, gA0 + (size_t)(32 * i) * K + k0);
            cp_async16(st + HM_TILE_B + so, gB0 + (size_t)(32 * i) * K + k0);
        }
    };

    load_stage(0, 0); cp_commit();
    load_stage(1, 1); cp_commit();

    int s = 0;
    for (int c = 0; c < nchunk; c++) {
        cp_wait1();
        __syncthreads();
        {
            int s2 = s + 2; if (s2 >= 3) s2 -= 3;
            if (c + 2 < nchunk) load_stage(s2, c + 2);
            cp_commit();
        }

        const uint32_t st = sbase + s * HM_STAGE;
        const uint32_t sA = st + aAddrBase;
        const uint32_t sB = st + HM_TILE_B + bAddrBase;

#pragma unroll
        for (int ks = 0; ks < 4; ks++) {
            const uint32_t ko = ks * 32;
            uint32_t a[2][4];
            ldsm4(a[0], sA + ko);
            ldsm4(a[1], sA + 16 * HM_ROWB + ko);
            uint32_t b0[4], b1[4];
            ldsm4(b0, sB + ko);                       // p = 0
#pragma unroll
            for (int p = 0; p < 4; p++) {
                uint32_t* bc = (p & 1) ? b1 : b0;
                uint32_t* bn = (p & 1) ? b0 : b1;
                if (p < 3)
                    ldsm4(bn, sB + (uint32_t)(p + 1) * 16 * HM_ROWB + ko);
#pragma unroll
                for (int m = 0; m < 2; m++) {
                    mma16816f16(acc[m][2 * p + 0], a[m], bc + 0);
                    mma16816f16(acc[m][2 * p + 1], a[m], bc + 2);
                }
            }
        }
        if (++s == 3) s = 0;
    }

    // fused RoPE (uniform per CTA: q/k head cols are [0,2560), 128-aligned)
    if (ROPE && bn < NH * HD + NKV * HD) {
        const int d0 = lane & 3;
#pragma unroll
        for (int m = 0; m < 2; m++) {
            const int r0 = bm + warpM * 32 + m * 16 + (lane >> 2);
#pragma unroll
            for (int n = 0; n < 8; n++) {
                const int d = n * 4 + d0;
                float2 cs0 = *reinterpret_cast<const float2*>(fc + (size_t)r0 * 64 + d * 2);
                float2 cs1 = *reinterpret_cast<const float2*>(fc + (size_t)(r0 + 8) * 64 + d * 2);
                float x0 = acc[m][n][0], x1 = acc[m][n][1];
                acc[m][n][0] = x0 * cs0.x - x1 * cs0.y;
                acc[m][n][1] = x1 * cs0.x + x0 * cs0.y;
                float y0 = acc[m][n][2], y1 = acc[m][n][3];
                acc[m][n][2] = y0 * cs1.x - y1 * cs1.y;
                acc[m][n][3] = y1 * cs1.x + y0 * cs1.y;
            }
        }
    }

    const int qrow = lane >> 2;
    const int qcol = (lane & 3) * 2;
#pragma unroll
    for (int m = 0; m < 2; m++) {
        const int row0 = bm + warpM * 32 + m * 16 + qrow;
#pragma unroll
        for (int n = 0; n < 8; n++) {
            const int col = bn + warpN * 64 + n * 8 + qcol;
            if (HALF_OUT) {
                __half* C = (__half*)Cv;
                *reinterpret_cast<uint32_t*>(C + (size_t)row0 * N + col) =
                    pack_h2(acc[m][n][0], acc[m][n][1]);
                *reinterpret_cast<uint32_t*>(C + (size_t)(row0 + 8) * N + col) =
                    pack_h2(acc[m][n][2], acc[m][n][3]);
            } else {
                float* C = (float*)Cv;
                *reinterpret_cast<float2*>(C + (size_t)row0 * N + col) =
                    make_float2(acc[m][n][0], acc[m][n][1]);
                *reinterpret_cast<float2*>(C + (size_t)(row0 + 8) * N + col) =
                    make_float2(acc[m][n][2], acc[m][n][3]);
            }
        }
    }
}

// ---------------------------------------------------------------------------
// HMMA flash attention, causal, GQA. Q-tile 128 rows, KV-tile 64.
// 8 warps, warp owns 16 full rows (FA-2, warp-local softmax).
// 3 KV stages, ONE sync + ONE wait per tile. b-fragment double buffers in
// both QK and PV mma loops; softmax row-group chains (i=0,1) interleaved
// stage-major to hide SHFL latency. LPT (longest-first) 1D grid.
// ---------------------------------------------------------------------------
#define FK_ROW  144
#define FK_TILE (64 * FK_ROW)                  // 9216 B
#define FQ_SZ   (128 * FK_ROW)                 // 18432 B
#define FK_STG  (2 * FK_TILE)                  // 18432 B
#define FK_SMEM (FQ_SZ + 3 * FK_STG)           // 73728 B
#define N_QT    (S_LEN / 128)                  // 16

__global__ __launch_bounds__(256, 2) void flash_hmma_kernel(
    const __half* __restrict__ qkvh, __half* __restrict__ Y)
{
    extern __shared__ char sm[];
    const uint32_t sb = smem_to_u32(sm);

    const int bx = blockIdx.x;
    const int qt = (N_QT - 1) - (bx >> 5);     // longest-first
    const int h  = bx & 31;
    const int kh = h >> 2;
    const int q0 = qt * 128;
    const int njt = 2 * qt + 2;                // >= 2 always

    const int tid  = threadIdx.x;
    const int w    = tid >> 5;
    const int lane = tid & 31;

    const float C2 = 0.18033688011112042f;   // (1/8) * log2(e)

    const uint32_t qAddr = (uint32_t)(w * 16 + (lane & 15)) * FK_ROW + (lane >> 4) * 16;
    const uint32_t kAddr = (uint32_t)(((lane >> 4) & 1) * 8 + (lane & 7)) * FK_ROW
                           + ((lane >> 3) & 1) * 16;
    const uint32_t vAddr = (uint32_t)((lane & 7) + ((lane >> 3) & 1) * 8) * FK_ROW
                           + (lane >> 4) * 16;

    auto load_q = [&]() {
#pragma unroll
        for (int i = 0; i < 4; i++) {
            int p = tid + i * 256, row = p >> 3, ch = p & 7;
            cp_async16(sb + (uint32_t)row * FK_ROW + ch * 16,
                       qkvh + (size_t)(q0 + row) * QKV_COLS + h * HD + ch * 8);
        }
    };
    auto load_kv = [&](int s, int jt) {
        const int j0 = jt * 64;
        const uint32_t Kb = sb + FQ_SZ + s * FK_STG;
#pragma unroll
        for (int i = 0; i < 2; i++) {
            int p = tid + i * 256, row = p >> 3, ch = p & 7;
            const __half* base = qkvh + (size_t)(j0 + row) * QKV_COLS + kh * HD + ch * 8;
            cp_async16(Kb + (uint32_t)row * FK_ROW + ch * 16, base + NH * HD);
            cp_async16(Kb + FK_TILE + (uint32_t)row * FK_ROW + ch * 16, base + (NH + NKV) * HD);
        }
    };

    load_q(); load_kv(0, 0); cp_commit();
    load_kv(1, 1); cp_commit();

    uint32_t aQ[4][4];
    float o[8][4];
#pragma unroll
    for (int n = 0; n < 8; n++)
#pragma unroll
        for (int q = 0; q < 4; q++) o[n][q] = 0.f;
    float m2[2] = { -1e30f, -1e30f };
    float l[2]  = { 0.f, 0.f };

    int s = 0;
    for (int jt = 0; jt < njt; jt++) {
        cp_wait1();
        __syncthreads();
        {
            int s2 = s + 2; if (s2 >= 3) s2 -= 3;
            if (jt + 2 < njt) load_kv(s2, jt + 2);
            cp_commit();
        }
        if (jt == 0) {
#pragma unroll
            for (int kc = 0; kc < 4; kc++) ldsm4(aQ[kc], sb + qAddr + kc * 32);
        }

        const uint32_t Kb = sb + FQ_SZ + s * FK_STG;
        const uint32_t Vb = Kb + FK_TILE;

        // --- scores: QK^T with b double buffer (t = p*4 + kc) ---
        float sc[8][4];
#pragma unroll
        for (int n = 0; n < 8; n++)
#pragma unroll
            for (int q = 0; q < 4; q++) sc[n][q] = 0.f;
        {
            uint32_t b0[4], b1[4];
            ldsm4(b0, Kb + kAddr);
#pragma unroll
            for (int t = 0; t < 16; t++) {
                const int p = t >> 2, kc = t & 3;
                uint32_t* bc = (t & 1) ? b1 : b0;
                uint32_t* bn = (t & 1) ? b0 : b1;
                if (t < 15) {
                    const int t2 = t + 1;
                    ldsm4(bn, Kb + kAddr + (uint32_t)(t2 >> 2) * 16 * FK_ROW
                                         + (uint32_t)(t2 & 3) * 32);
                }
                mma16816f16(sc[2 * p + 0], aQ[kc], bc + 0);
                mma16816f16(sc[2 * p + 1], aQ[kc], bc + 2);
            }
        }

        // causal mask (sentinel -500 keeps the unclamped packed exp2 in-range)
        if (jt >= 2 * qt) {
            const int j0 = jt * 64;
            const int rg = q0 + w * 16 + (lane >> 2);
            const int cb = j0 + (lane & 3) * 2;
#pragma unroll
            for (int n = 0; n < 8; n++) {
#pragma unroll
                for (int e = 0; e < 2; e++) {
                    int cg = cb + n * 8 + e;
                    if (cg > rg)     sc[n][e]     = -500.f;
                    if (cg > rg + 8) sc[n][e + 2] = -500.f;
                }
            }
        }

        // --- online softmax (log2 domain), both row groups interleaved ---
        uint32_t ph[8][2];
        {
            float mr[2], m2n[2], r[2], sum[2];
            u64 NM2[2];
#pragma unroll
            for (int i = 0; i < 2; i++) {
                float m_ = -1e30f;
#pragma unroll
                for (int n = 0; n < 8; n++)
                    m_ = fmaxf(m_, fmaxf(sc[n][2 * i], sc[n][2 * i + 1]));
                mr[i] = m_;
            }
#pragma unroll
            for (int i = 0; i < 2; i++)
                mr[i] = fmaxf(mr[i], __shfl_xor_sync(0xffffffffu, mr[i], 1));
#pragma unroll
            for (int i = 0; i < 2; i++)
                mr[i] = fmaxf(mr[i], __shfl_xor_sync(0xffffffffu, mr[i], 2));
#pragma unroll
            for (int i = 0; i < 2; i++) {
                m2n[i] = fmaxf(m2[i], mr[i] * C2);
                r[i]   = fexp2(m2[i] - m2n[i]);
                m2[i]  = m2n[i];
                NM2[i] = dup2(-m2n[i]);
                sum[i] = 0.f;
            }
            const u64 kSC = dup2(C2);
#pragma unroll
            for (int n = 0; n < 8; n++) {
#pragma unroll
                for (int i = 0; i < 2; i++) {
                    u64 s2  = pk2(sc[n][2 * i], sc[n][2 * i + 1]);
                    u64 arg = fma2_(s2, kSC, NM2[i]);
                    float p0, p1;
                    FEXP2X2(arg, p0, p1);
                    sum[i] += p0 + p1;
                    ph[n][i] = pack_h2(p0, p1);
                }
            }
#pragma unroll
            for (int i = 0; i < 2; i++)
                sum[i] += __shfl_xor_sync(0xffffffffu, sum[i], 1);
#pragma unroll
            for (int i = 0; i < 2; i++)
                sum[i] += __shfl_xor_sync(0xffffffffu, sum[i], 2);
#pragma unroll
            for (int i = 0; i < 2; i++)
                l[i] = l[i] * r[i] + sum[i];
#pragma unroll
            for (int n = 0; n < 8; n++) {
#pragma unroll
                for (int i = 0; i < 2; i++) {
                    o[n][2 * i]     *= r[i];
                    o[n][2 * i + 1] *= r[i];
                }
            }
        }

        // --- O += P @ V with b double buffer (t = kc*4 + vp) ---
        {
            uint32_t b0[4], b1[4];
            ldsm4t(b0, Vb + vAddr);
#pragma unroll
            for (int t = 0; t < 16; t++) {
                const int kc = t >> 2, vp = t & 3;
                uint32_t* bc = (t & 1) ? b1 : b0;
                uint32_t* bn = (t & 1) ? b0 : b1;
                if (t < 15) {
                    const int t2 = t + 1;
                    ldsm4t(bn, Vb + vAddr + (uint32_t)(t2 >> 2) * 16 * FK_ROW
                                          + (uint32_t)(t2 & 3) * 32);
                }
                uint32_t a[4] = { ph[2 * kc][0], ph[2 * kc][1],
                                  ph[2 * kc + 1][0], ph[2 * kc + 1][1] };
                mma16816f16(o[2 * vp + 0], a, bc + 0);
                mma16816f16(o[2 * vp + 1], a, bc + 2);
            }
        }

        if (++s == 3) s = 0;
    }

    // epilogue: fp16 y
#pragma unroll
    for (int i = 0; i < 2; i++) {
        float inv = 1.f / l[i];
        int row = q0 + w * 16 + (lane >> 2) + 8 * i;
        __half* yr = Y + (size_t)row * H_DIM + h * HD + (lane & 3) * 2;
#pragma unroll
        for (int n = 0; n < 8; n++) {
            __half2 v = __floats2half2_rn(o[n][2 * i] * inv, o[n][2 * i + 1] * inv);
            *reinterpret_cast<__half2*>(yr + n * 8) = v;
        }
    }
}

// ---------------------------------------------------------------------------
// kernel_launch: 4 launches total
// ---------------------------------------------------------------------------
extern "C" void kernel_launch(void* const* d_in, const int* in_sizes, int n_in,
                              void* d_out, int out_size)
{
    const float* x    = (const float*)d_in[0];
    const float* fc   = (const float*)d_in[1];
    const float* Wqkv = (const float*)d_in[3];
    const float* Wo   = (const float*)d_in[4];
    float* out = (float*)d_out;

    __half *qkvh, *ga, *gb, *gc;
    cudaGetSymbolAddress((void**)&qkvh, g_qkvh);
    cudaGetSymbolAddress((void**)&ga, g_a);
    cudaGetSymbolAddress((void**)&gb, g_b);
    cudaGetSymbolAddress((void**)&gc, g_c);

    cudaFuncSetAttribute((const void*)hgemm_kernel<true, true>,
                         cudaFuncAttributeMaxDynamicSharedMemorySize, HM_SMEM);
    cudaFuncSetAttribute((const void*)hgemm_kernel<false, false>,
                         cudaFuncAttributeMaxDynamicSharedMemorySize, HM_SMEM);
    cudaFuncSetAttribute((const void*)flash_hmma_kernel,
                         cudaFuncAttributeMaxDynamicSharedMemorySize, FK_SMEM);

    // 1) fused convert: x, Wqkv, Wo -> fp16
    cvt_all_kernel<<<CVT_BLOCKS, 256>>>(
        (const float4*)x, (const float4*)Wqkv, (const float4*)Wo,
        (uint2*)ga, (uint2*)gb, (uint2*)gc);

    // 2) QKV projection with fused RoPE, fp16 output
    {
        dim3 grid(QKV_COLS / 128, S_LEN / 128);
        hgemm_kernel<true, true><<<grid, 256, HM_SMEM>>>(
            ga, gb, qkvh, fc, S_LEN, QKV_COLS, H_DIM);
    }

    // 3) HMMA flash attention (q-tile 128, LPT order) -> g_a (fp16 y)
    flash_hmma_kernel<<<N_QT * NH, 256, FK_SMEM>>>(qkvh, ga);

    // 4) output projection, fp32 output: out = y @ Wo^T
    {
        dim3 grid(H_DIM / 128, S_LEN / 128);
        hgemm_kernel<false, false><<<grid, 256, HM_SMEM>>>(
            ga, gc, out, nullptr, S_LEN, H_DIM, H_DIM);
    }
}